// round 8
// baseline (speedup 1.0000x reference)
#include <cuda_runtime.h>
#include <cuda_bf16.h>
#include <math.h>
#include <stdio.h>
#include <stdint.h>

// Dims
#define BHN 32
#define TD 1024
#define SD 1024
#define HCD 128
#define QTILE 32           // q rows per CTA
#define NCH 8              // S chunks of 128

// smem strides (elements)
#define QS 136             // q tile row stride, bf16 (32 x 136)
#define KS 136             // k/vt tile row stride, bf16 (128 x 136)
#define PS 1036            // score/e/r row stride, f32 (32 x 1036)

#define SMEM_P_BYTES  (QTILE * PS * 4)            // 132,608
#define SMEM_Q_BYTES  (QTILE * QS * 2)            //   8,704
#define SMEM_K_BYTES  (128 * KS * 2)              //  34,816
#define SMEM_TOTAL    (SMEM_P_BYTES + SMEM_Q_BYTES + SMEM_K_BYTES)  // 176,128

__device__ __forceinline__ void mma16816(float c[4], const uint32_t a[4], const uint32_t b[2])
{
    asm volatile(
        "mma.sync.aligned.m16n8k16.row.col.f32.bf16.bf16.f32 "
        "{%0,%1,%2,%3}, {%4,%5,%6,%7}, {%8,%9}, {%0,%1,%2,%3};\n"
        : "+f"(c[0]), "+f"(c[1]), "+f"(c[2]), "+f"(c[3])
        : "r"(a[0]), "r"(a[1]), "r"(a[2]), "r"(a[3]), "r"(b[0]), "r"(b[1]));
}

__device__ __forceinline__ uint32_t f2bf2(float lo, float hi)
{
    __nv_bfloat162 h = __floats2bfloat162_rn(lo, hi);
    return *(uint32_t*)&h;
}

__global__ __launch_bounds__(256)
void fused_attn(const int* __restrict__ qq, const int* __restrict__ qsh,
                const int* __restrict__ kq, const int* __restrict__ ksh,
                const int* __restrict__ vq, const int* __restrict__ vsh,
                float* __restrict__ out)               // <-- float32 output
{
    extern __shared__ char sm[];
    float*         Ps = (float*)sm;                                  // 32 x PS f32
    __nv_bfloat16* Qs = (__nv_bfloat16*)(sm + SMEM_P_BYTES);         // 32 x QS bf16
    __nv_bfloat16* Kvs = (__nv_bfloat16*)(sm + SMEM_P_BYTES + SMEM_Q_BYTES); // 128 x KS

    const int bh   = blockIdx.y;
    const int t0   = blockIdx.x * QTILE;
    const int tid  = threadIdx.x;
    const int lane = tid & 31;
    const int wid  = tid >> 5;
    const int wm   = wid & 1;           // m-half (16 rows)
    const int wn   = wid >> 1;          // 0..3 (32-col slice)
    const int fr   = lane >> 2;         // fragment row 0..7
    const int fc   = (lane & 3) << 1;   // fragment col {0,2,4,6}

    // ---------------- load + dequant q tile (32 x 128) ----------------
    {
        const int* qb = qq  + ((size_t)bh * TD + t0) * HCD;
        const int* sb = qsh + ((size_t)bh * TD + t0) * (HCD / 8);
        for (int u = tid; u < QTILE * (HCD / 4); u += 256) {   // 1024 int4s
            int row = u >> 5, c4 = u & 31;
            int4 v = *(const int4*)(qb + (size_t)row * HCD + c4 * 4);
            int m = 1 << (sb[row * 16 + (c4 >> 1)] & 31);
            __nv_bfloat16 o[4];
            o[0] = __float2bfloat16_rn((float)(v.x * m));
            o[1] = __float2bfloat16_rn((float)(v.y * m));
            o[2] = __float2bfloat16_rn((float)(v.z * m));
            o[3] = __float2bfloat16_rn((float)(v.w * m));
            *(uint2*)&Qs[row * QS + c4 * 4] = *(const uint2*)o;
        }
    }
    __syncthreads();

    // ---------------- QK: 8 chunks of 128 s, scores -> Ps --------------
    for (int ch = 0; ch < NCH; ch++) {
        const int* kb = kq  + ((size_t)bh * SD + ch * 128) * HCD;
        const int* sb = ksh + ((size_t)bh * SD + ch * 128) * (HCD / 8);
        for (int u = tid; u < 128 * (HCD / 4); u += 256) {     // 4096 int4s
            int row = u >> 5, c4 = u & 31;
            int4 v = *(const int4*)(kb + (size_t)row * HCD + c4 * 4);
            int m = 1 << (sb[row * 16 + (c4 >> 1)] & 31);
            __nv_bfloat16 o[4];
            o[0] = __float2bfloat16_rn((float)(v.x * m));
            o[1] = __float2bfloat16_rn((float)(v.y * m));
            o[2] = __float2bfloat16_rn((float)(v.z * m));
            o[3] = __float2bfloat16_rn((float)(v.w * m));
            *(uint2*)&Kvs[row * KS + c4 * 4] = *(const uint2*)o;
        }
        __syncthreads();

        float acc[4][4];
#pragma unroll
        for (int nt = 0; nt < 4; nt++)
#pragma unroll
            for (int i = 0; i < 4; i++) acc[nt][i] = 0.f;

#pragma unroll
        for (int kk = 0; kk < 128; kk += 16) {
            uint32_t a[4];
            int ab = (wm * 16 + fr) * QS + kk + fc;
            a[0] = *(const uint32_t*)&Qs[ab];
            a[1] = *(const uint32_t*)&Qs[ab + 8 * QS];
            a[2] = *(const uint32_t*)&Qs[ab + 8];
            a[3] = *(const uint32_t*)&Qs[ab + 8 * QS + 8];
#pragma unroll
            for (int nt = 0; nt < 4; nt++) {
                int bb = (wn * 32 + nt * 8 + fr) * KS + kk + fc;
                uint32_t b[2] = { *(const uint32_t*)&Kvs[bb],
                                  *(const uint32_t*)&Kvs[bb + 8] };
                mma16816(acc[nt], a, b);
            }
        }
#pragma unroll
        for (int nt = 0; nt < 4; nt++) {
            int col = ch * 128 + wn * 32 + nt * 8 + fc;
            int r0 = (wm * 16 + fr) * PS;
            Ps[r0 + col]              = acc[nt][0];
            Ps[r0 + col + 1]          = acc[nt][1];
            Ps[r0 + 8 * PS + col]     = acc[nt][2];
            Ps[r0 + 8 * PS + col + 1] = acc[nt][3];
        }
        __syncthreads();   // Kvs reused next chunk
    }

    // ---------------- softmax + integer requant, in place in Ps --------
    // 8 threads per row; thread handles s = tr + 8*j (one elem of each group j)
    {
        const float SCALE = (float)(6.103515625e-05 / sqrt(128.0)); // f32(2^-14/sqrt(HC))
        const int srow = wid * 4 + (lane >> 3);   // 0..31
        const int tr   = lane & 7;
        float* P = Ps + srow * PS;

        float mx = -3.0e38f;
        for (int j = 0; j < 128; j++) mx = fmaxf(mx, P[tr + 8 * j]);
        mx = fmaxf(mx, __shfl_xor_sync(0xffffffffu, mx, 1));
        mx = fmaxf(mx, __shfl_xor_sync(0xffffffffu, mx, 2));
        mx = fmaxf(mx, __shfl_xor_sync(0xffffffffu, mx, 4));
        const float lm = mx * SCALE;

        float sum = 0.f;
        for (int j = 0; j < 128; j++) {
            float l = P[tr + 8 * j] * SCALE;
            float e = expf(l - lm);                 // full sum — matches reference
            P[tr + 8 * j] = e;
            sum += e;
        }
        sum += __shfl_xor_sync(0xffffffffu, sum, 1);
        sum += __shfl_xor_sync(0xffffffffu, sum, 2);
        sum += __shfl_xor_sync(0xffffffffu, sum, 4);

        for (int j = 0; j < 128; j++) {
            float e   = P[tr + 8 * j];
            float val = rintf(__fdiv_rn(e, sum) * 16384.0f);    // half-even == jnp.round
            float g = val;
            g = fmaxf(g, __shfl_xor_sync(0xffffffffu, g, 1));
            g = fmaxf(g, __shfl_xor_sync(0xffffffffu, g, 2));
            g = fmaxf(g, __shfl_xor_sync(0xffffffffu, g, 4));
            int gi = (int)g;                                    // <= 16384
            int k = 0;
            while (gi > (255 << k)) k++;                        // == clip(ceil(log2(g/255)),0)
            float dn = __int_as_float((127 - k) << 23);         // exact 2^-k
            float up = __int_as_float((127 + k) << 23);         // exact 2^k
            float r  = fminf(rintf(val * dn), 255.0f) * up;     // exact 8-bit*po2
            P[tr + 8 * j] = r;
        }
    }
    __syncthreads();

    // ---------------- RV: 8 vt chunks, r-frags from Ps -----------------
    float racc[4][4];
#pragma unroll
    for (int nt = 0; nt < 4; nt++)
#pragma unroll
        for (int i = 0; i < 4; i++) racc[nt][i] = 0.f;

    for (int ch = 0; ch < NCH; ch++) {
        const int* vb = vq  + (size_t)bh * HCD * SD + ch * 128;
        const int* sb = vsh + (size_t)bh * HCD * (SD / 8) + ch * 16;
        for (int u = tid; u < 128 * 32; u += 256) {            // rows=c, 32 int4 of s
            int row = u >> 5, s4 = u & 31;
            int4 v = *(const int4*)(vb + (size_t)row * SD + s4 * 4);
            int m = 1 << (sb[row * (SD / 8) + (s4 >> 1)] & 31);
            __nv_bfloat16 o[4];
            o[0] = __float2bfloat16_rn((float)(v.x * m));
            o[1] = __float2bfloat16_rn((float)(v.y * m));
            o[2] = __float2bfloat16_rn((float)(v.z * m));
            o[3] = __float2bfloat16_rn((float)(v.w * m));
            *(uint2*)&Kvs[row * KS + s4 * 4] = *(const uint2*)o;
        }
        __syncthreads();

#pragma unroll
        for (int kk = 0; kk < 128; kk += 16) {
            int scol = ch * 128 + kk;
            int r0 = (wm * 16 + fr) * PS + scol + fc;
            float2 p00 = *(const float2*)&Ps[r0];
            float2 p10 = *(const float2*)&Ps[r0 + 8 * PS];
            float2 p01 = *(const float2*)&Ps[r0 + 8];
            float2 p11 = *(const float2*)&Ps[r0 + 8 * PS + 8];
            uint32_t a[4] = { f2bf2(p00.x, p00.y), f2bf2(p10.x, p10.y),
                              f2bf2(p01.x, p01.y), f2bf2(p11.x, p11.y) };
#pragma unroll
            for (int nt = 0; nt < 4; nt++) {
                int bb = (wn * 32 + nt * 8 + fr) * KS + kk + fc;
                uint32_t b[2] = { *(const uint32_t*)&Kvs[bb],
                                  *(const uint32_t*)&Kvs[bb + 8] };
                mma16816(racc[nt], a, b);
            }
        }
        __syncthreads();
    }

    // ---------------- epilogue: float32 output (rounded to integer) ----
#pragma unroll
    for (int nt = 0; nt < 4; nt++) {
        int row = t0 + wm * 16 + fr;
        int col = wn * 32 + nt * 8 + fc;
        size_t base = (size_t)bh * TD * HCD;
        out[base + (size_t)row * HCD + col]           = rintf(racc[nt][0]);
        out[base + (size_t)row * HCD + col + 1]       = rintf(racc[nt][1]);
        out[base + (size_t)(row + 8) * HCD + col]     = rintf(racc[nt][2]);
        out[base + (size_t)(row + 8) * HCD + col + 1] = rintf(racc[nt][3]);
    }
}

// ---------------------------------------------------------------------------
static void diag_sync(const char* stage)
{
    cudaStreamCaptureStatus st = cudaStreamCaptureStatusNone;
    cudaStreamIsCapturing(0, &st);
    if (st == cudaStreamCaptureStatusNone) {          // never sync during capture
        cudaError_t e = cudaStreamSynchronize(0);
        if (e != cudaSuccess)
            fprintf(stderr, "[kl] stage %s: %s\n", stage, cudaGetErrorString(e));
    }
}

extern "C" void kernel_launch(void* const* d_in, const int* in_sizes, int n_in,
                              void* d_out, int out_size)
{
    if (n_in < 6) { fprintf(stderr, "[kl] bad n_in=%d\n", n_in); return; }

    const int* qq  = (const int*)d_in[0];
    const int* qsh = (const int*)d_in[1];
    const int* kq  = (const int*)d_in[2];
    const int* ksh = (const int*)d_in[3];
    const int* vq  = (const int*)d_in[4];
    const int* vsh = (const int*)d_in[5];

    cudaError_t e = cudaFuncSetAttribute(fused_attn,
        cudaFuncAttributeMaxDynamicSharedMemorySize, SMEM_TOTAL);
    if (e != cudaSuccess)
        fprintf(stderr, "[kl] attr: %s\n", cudaGetErrorString(e));

    dim3 grid(TD / QTILE, BHN);     // 32 x 32
    fused_attn<<<grid, 256, SMEM_TOTAL>>>(qq, qsh, kq, ksh, vq, vsh,
                                          (float*)d_out);
    diag_sync("fused_attn");
}

// round 9
// speedup vs baseline: 1.3575x; 1.3575x over previous
#include <cuda_runtime.h>
#include <cuda_bf16.h>
#include <math.h>
#include <stdio.h>
#include <stdint.h>

// Dims
#define BHN 32
#define TD 1024
#define SD 1024
#define HCD 128
#define QTILE 32           // q rows per CTA
#define NCH 8              // S chunks of 128
#define THREADS 512        // 16 warps

// smem strides (elements)
#define QS 136             // q tile row stride, bf16
#define KS 136             // k/vt tile row stride, bf16
#define PS 1036            // score/e/r row stride, f32

#define SMEM_P_BYTES  (QTILE * PS * 4)            // 132,608
#define SMEM_Q_BYTES  (QTILE * QS * 2)            //   8,704
#define SMEM_K_BYTES  (128 * KS * 2)              //  34,816 per buffer
#define SMEM_TOTAL    (SMEM_P_BYTES + SMEM_Q_BYTES + 2 * SMEM_K_BYTES) // 210,944

__device__ __forceinline__ void mma16816(float c[4], const uint32_t a[4], const uint32_t b[2])
{
    asm volatile(
        "mma.sync.aligned.m16n8k16.row.col.f32.bf16.bf16.f32 "
        "{%0,%1,%2,%3}, {%4,%5,%6,%7}, {%8,%9}, {%0,%1,%2,%3};\n"
        : "+f"(c[0]), "+f"(c[1]), "+f"(c[2]), "+f"(c[3])
        : "r"(a[0]), "r"(a[1]), "r"(a[2]), "r"(a[3]), "r"(b[0]), "r"(b[1]));
}

__device__ __forceinline__ uint32_t f2bf2(float lo, float hi)
{
    __nv_bfloat162 h = __floats2bfloat162_rn(lo, hi);
    return *(uint32_t*)&h;
}

__global__ __launch_bounds__(THREADS)
void fused_attn(const int* __restrict__ qq, const int* __restrict__ qsh,
                const int* __restrict__ kq, const int* __restrict__ ksh,
                const int* __restrict__ vq, const int* __restrict__ vsh,
                float* __restrict__ out)
{
    extern __shared__ char sm[];
    float*         Ps  = (float*)sm;                                   // 32 x PS f32
    __nv_bfloat16* Qs  = (__nv_bfloat16*)(sm + SMEM_P_BYTES);          // 32 x QS
    __nv_bfloat16* Kv0 = (__nv_bfloat16*)(sm + SMEM_P_BYTES + SMEM_Q_BYTES);
    __nv_bfloat16* Kv1 = Kv0 + 128 * KS;

    const int bh   = blockIdx.y;
    const int t0   = blockIdx.x * QTILE;
    const int tid  = threadIdx.x;
    const int lane = tid & 31;
    const int wid  = tid >> 5;
    const int wm   = wid & 1;           // m-half (16 rows)
    const int wn   = wid >> 1;          // 0..7 (16-col slice)
    const int fr   = lane >> 2;         // fragment row 0..7
    const int fc   = (lane & 3) << 1;   // fragment col {0,2,4,6}

    // ---------------- load + dequant q tile (32 x 128) ----------------
    {
        const int* qb = qq  + ((size_t)bh * TD + t0) * HCD;
        const int* sb = qsh + ((size_t)bh * TD + t0) * (HCD / 8);
#pragma unroll
        for (int i = 0; i < 2; i++) {                      // 1024 int4 / 512 thr
            int u = tid + i * THREADS;
            int row = u >> 5, c4 = u & 31;
            int4 v = *(const int4*)(qb + (size_t)row * HCD + c4 * 4);
            int m = 1 << (sb[row * 16 + (c4 >> 1)] & 31);
            __nv_bfloat16 o[4];
            o[0] = __float2bfloat16_rn((float)(v.x * m));
            o[1] = __float2bfloat16_rn((float)(v.y * m));
            o[2] = __float2bfloat16_rn((float)(v.z * m));
            o[3] = __float2bfloat16_rn((float)(v.w * m));
            *(uint2*)&Qs[row * QS + c4 * 4] = *(const uint2*)o;
        }
    }

    // register prefetch state: 8 int4 + 8 scales per thread per chunk
    int4 pre[8];
    int  psh[8];

    // K chunk: 128 rows x 128 cols -> 4096 int4
#define LOAD_K(CH)                                                        \
    {                                                                     \
        const int* kb_ = kq  + ((size_t)bh * SD + (CH) * 128) * HCD;      \
        const int* sb_ = ksh + ((size_t)bh * SD + (CH) * 128) * 16;       \
        _Pragma("unroll")                                                 \
        for (int i = 0; i < 8; i++) {                                     \
            int u = tid + i * THREADS;                                    \
            int row = u >> 5, c4 = u & 31;                                \
            pre[i] = *(const int4*)(kb_ + (size_t)row * HCD + c4 * 4);    \
            psh[i] = sb_[row * 16 + (c4 >> 1)];                           \
        }                                                                 \
    }

    // VT chunk: 128 rows(c) x 128 s -> 4096 int4
#define LOAD_V(CH)                                                        \
    {                                                                     \
        const int* vb_ = vq  + (size_t)bh * HCD * SD + (CH) * 128;        \
        const int* sb_ = vsh + (size_t)bh * HCD * (SD / 8) + (CH) * 16;   \
        _Pragma("unroll")                                                 \
        for (int i = 0; i < 8; i++) {                                     \
            int u = tid + i * THREADS;                                    \
            int row = u >> 5, s4 = u & 31;                                \
            pre[i] = *(const int4*)(vb_ + (size_t)row * SD + s4 * 4);     \
            psh[i] = sb_[row * (SD / 8) + (s4 >> 1)];                     \
        }                                                                 \
    }

#define STS_KV(BUF)                                                       \
    {                                                                     \
        _Pragma("unroll")                                                 \
        for (int i = 0; i < 8; i++) {                                     \
            int u = tid + i * THREADS;                                    \
            int row = u >> 5, c4 = u & 31;                                \
            int m = 1 << (psh[i] & 31);                                   \
            __nv_bfloat16 o[4];                                           \
            o[0] = __float2bfloat16_rn((float)(pre[i].x * m));            \
            o[1] = __float2bfloat16_rn((float)(pre[i].y * m));            \
            o[2] = __float2bfloat16_rn((float)(pre[i].z * m));            \
            o[3] = __float2bfloat16_rn((float)(pre[i].w * m));            \
            *(uint2*)&(BUF)[row * KS + c4 * 4] = *(const uint2*)o;        \
        }                                                                 \
    }

    // ---------------- QK: ping-pong double buffer ----------------------
    LOAD_K(0);
    STS_KV(Kv0);
    __syncthreads();

    for (int ch = 0; ch < NCH; ch++) {
        if (ch + 1 < NCH) LOAD_K(ch + 1);            // issue LDGs early
        const __nv_bfloat16* cur = (ch & 1) ? Kv1 : Kv0;

        float acc[2][4];
#pragma unroll
        for (int nt = 0; nt < 2; nt++)
#pragma unroll
            for (int i = 0; i < 4; i++) acc[nt][i] = 0.f;

#pragma unroll
        for (int kk = 0; kk < 128; kk += 16) {
            uint32_t a[4];
            int ab = (wm * 16 + fr) * QS + kk + fc;
            a[0] = *(const uint32_t*)&Qs[ab];
            a[1] = *(const uint32_t*)&Qs[ab + 8 * QS];
            a[2] = *(const uint32_t*)&Qs[ab + 8];
            a[3] = *(const uint32_t*)&Qs[ab + 8 * QS + 8];
#pragma unroll
            for (int nt = 0; nt < 2; nt++) {
                int bb = (wn * 16 + nt * 8 + fr) * KS + kk + fc;
                uint32_t b[2] = { *(const uint32_t*)&cur[bb],
                                  *(const uint32_t*)&cur[bb + 8] };
                mma16816(acc[nt], a, b);
            }
        }
#pragma unroll
        for (int nt = 0; nt < 2; nt++) {
            int col = ch * 128 + wn * 16 + nt * 8 + fc;
            int r0 = (wm * 16 + fr) * PS;
            Ps[r0 + col]              = acc[nt][0];
            Ps[r0 + col + 1]          = acc[nt][1];
            Ps[r0 + 8 * PS + col]     = acc[nt][2];
            Ps[r0 + 8 * PS + col + 1] = acc[nt][3];
        }
        if (ch + 1 < NCH) STS_KV((ch & 1) ? Kv0 : Kv1);
        __syncthreads();
    }

    // prefetch V chunk 0 — latency hides behind softmax
    LOAD_V(0);

    // ---------------- softmax + integer requant, in place in Ps --------
    // 16 threads per row; thread handles s = tr + 16*j
    {
        const float SCALE = (float)(6.103515625e-05 / sqrt(128.0)); // f32(2^-14/sqrt(HC))
        const int srow = tid >> 4;      // 0..31
        const int tr   = tid & 15;
        float* P = Ps + srow * PS;

        float mx = -3.0e38f;
#pragma unroll 4
        for (int j = 0; j < 64; j++) mx = fmaxf(mx, P[tr + 16 * j]);
        mx = fmaxf(mx, __shfl_xor_sync(0xffffffffu, mx, 1));
        mx = fmaxf(mx, __shfl_xor_sync(0xffffffffu, mx, 2));
        mx = fmaxf(mx, __shfl_xor_sync(0xffffffffu, mx, 4));
        mx = fmaxf(mx, __shfl_xor_sync(0xffffffffu, mx, 8));
        const float lm = mx * SCALE;

        float sum = 0.f;
#pragma unroll 4
        for (int j = 0; j < 64; j++) {
            float l = P[tr + 16 * j] * SCALE;
            float e = expf(l - lm);
            P[tr + 16 * j] = e;
            sum += e;
        }
        sum += __shfl_xor_sync(0xffffffffu, sum, 1);
        sum += __shfl_xor_sync(0xffffffffu, sum, 2);
        sum += __shfl_xor_sync(0xffffffffu, sum, 4);
        sum += __shfl_xor_sync(0xffffffffu, sum, 8);

        // group of 8: elements with same (tr>>3) across tr low 3 bits
#pragma unroll 2
        for (int j = 0; j < 64; j++) {
            float e   = P[tr + 16 * j];
            float val = rintf(__fdiv_rn(e, sum) * 16384.0f);    // half-even == jnp.round
            float g = val;
            g = fmaxf(g, __shfl_xor_sync(0xffffffffu, g, 1));
            g = fmaxf(g, __shfl_xor_sync(0xffffffffu, g, 2));
            g = fmaxf(g, __shfl_xor_sync(0xffffffffu, g, 4));
            int gi = (int)g;                                    // <= 16384
            int k = 0;
            while (gi > (255 << k)) k++;                        // clip(ceil(log2(g/255)),0)
            float dn = __int_as_float((127 - k) << 23);         // exact 2^-k
            float up = __int_as_float((127 + k) << 23);         // exact 2^k
            float r  = fminf(rintf(val * dn), 255.0f) * up;     // exact 8-bit*po2
            P[tr + 16 * j] = r;
        }
    }
    STS_KV(Kv0);
    __syncthreads();

    // ---------------- RV: ping-pong, r-frags from Ps -------------------
    float racc[2][4];
#pragma unroll
    for (int nt = 0; nt < 2; nt++)
#pragma unroll
        for (int i = 0; i < 4; i++) racc[nt][i] = 0.f;

    for (int ch = 0; ch < NCH; ch++) {
        if (ch + 1 < NCH) LOAD_V(ch + 1);
        const __nv_bfloat16* cur = (ch & 1) ? Kv1 : Kv0;

#pragma unroll
        for (int kk = 0; kk < 128; kk += 16) {
            int r0 = (wm * 16 + fr) * PS + ch * 128 + kk + fc;
            float2 p00 = *(const float2*)&Ps[r0];
            float2 p10 = *(const float2*)&Ps[r0 + 8 * PS];
            float2 p01 = *(const float2*)&Ps[r0 + 8];
            float2 p11 = *(const float2*)&Ps[r0 + 8 * PS + 8];
            uint32_t a[4] = { f2bf2(p00.x, p00.y), f2bf2(p10.x, p10.y),
                              f2bf2(p01.x, p01.y), f2bf2(p11.x, p11.y) };
#pragma unroll
            for (int nt = 0; nt < 2; nt++) {
                int bb = (wn * 16 + nt * 8 + fr) * KS + kk + fc;
                uint32_t b[2] = { *(const uint32_t*)&cur[bb],
                                  *(const uint32_t*)&cur[bb + 8] };
                mma16816(racc[nt], a, b);
            }
        }
        if (ch + 1 < NCH) STS_KV((ch & 1) ? Kv0 : Kv1);
        __syncthreads();
    }

    // ---------------- epilogue: float32 output (rounded) ---------------
#pragma unroll
    for (int nt = 0; nt < 2; nt++) {
        int row = t0 + wm * 16 + fr;
        int col = wn * 16 + nt * 8 + fc;
        size_t base = (size_t)bh * TD * HCD;
        out[base + (size_t)row * HCD + col]           = rintf(racc[nt][0]);
        out[base + (size_t)row * HCD + col + 1]       = rintf(racc[nt][1]);
        out[base + (size_t)(row + 8) * HCD + col]     = rintf(racc[nt][2]);
        out[base + (size_t)(row + 8) * HCD + col + 1] = rintf(racc[nt][3]);
    }
}

// ---------------------------------------------------------------------------
static void diag_sync(const char* stage)
{
    cudaStreamCaptureStatus st = cudaStreamCaptureStatusNone;
    cudaStreamIsCapturing(0, &st);
    if (st == cudaStreamCaptureStatusNone) {
        cudaError_t e = cudaStreamSynchronize(0);
        if (e != cudaSuccess)
            fprintf(stderr, "[kl] stage %s: %s\n", stage, cudaGetErrorString(e));
    }
}

extern "C" void kernel_launch(void* const* d_in, const int* in_sizes, int n_in,
                              void* d_out, int out_size)
{
    if (n_in < 6) { fprintf(stderr, "[kl] bad n_in=%d\n", n_in); return; }

    const int* qq  = (const int*)d_in[0];
    const int* qsh = (const int*)d_in[1];
    const int* kq  = (const int*)d_in[2];
    const int* ksh = (const int*)d_in[3];
    const int* vq  = (const int*)d_in[4];
    const int* vsh = (const int*)d_in[5];

    cudaError_t e = cudaFuncSetAttribute(fused_attn,
        cudaFuncAttributeMaxDynamicSharedMemorySize, SMEM_TOTAL);
    if (e != cudaSuccess)
        fprintf(stderr, "[kl] attr: %s\n", cudaGetErrorString(e));

    dim3 grid(TD / QTILE, BHN);     // 32 x 32
    fused_attn<<<grid, THREADS, SMEM_TOTAL>>>(qq, qsh, kq, ksh, vq, vsh,
                                              (float*)d_out);
    diag_sync("fused_attn");
}

// round 10
// speedup vs baseline: 1.4953x; 1.1015x over previous
#include <cuda_runtime.h>
#include <cuda_bf16.h>
#include <math.h>
#include <stdio.h>
#include <stdint.h>

// Dims
#define BHN 32
#define TD 1024
#define SD 1024
#define HCD 128
#define QTILE 32           // q rows per CTA
#define NCH 8              // S chunks of 128
#define THREADS 512        // 16 warps

// smem strides (elements)
#define QS 136             // q tile row stride, bf16
#define KS 136             // k/vt tile row stride, bf16
#define PS 1036            // score/e/r row stride, f32

#define SMEM_P_BYTES  (QTILE * PS * 4)            // 132,608
#define SMEM_Q_BYTES  (QTILE * QS * 2)            //   8,704
#define SMEM_K_BYTES  (128 * KS * 2)              //  34,816 per buffer
#define SMEM_TOTAL    (SMEM_P_BYTES + SMEM_Q_BYTES + 2 * SMEM_K_BYTES) // 210,944

__device__ __forceinline__ void mma16816(float c[4], const uint32_t a[4], const uint32_t b[2])
{
    asm volatile(
        "mma.sync.aligned.m16n8k16.row.col.f32.bf16.bf16.f32 "
        "{%0,%1,%2,%3}, {%4,%5,%6,%7}, {%8,%9}, {%0,%1,%2,%3};\n"
        : "+f"(c[0]), "+f"(c[1]), "+f"(c[2]), "+f"(c[3])
        : "r"(a[0]), "r"(a[1]), "r"(a[2]), "r"(a[3]), "r"(b[0]), "r"(b[1]));
}

__device__ __forceinline__ void ldsm_x4(uint32_t r[4], uint32_t addr)
{
    asm volatile("ldmatrix.sync.aligned.m8n8.x4.shared.b16 {%0,%1,%2,%3}, [%4];"
                 : "=r"(r[0]), "=r"(r[1]), "=r"(r[2]), "=r"(r[3]) : "r"(addr));
}

__device__ __forceinline__ uint32_t smem_u32(const void* p)
{
    return (uint32_t)__cvta_generic_to_shared(p);
}

__device__ __forceinline__ uint32_t f2bf2(float lo, float hi)
{
    __nv_bfloat162 h = __floats2bfloat162_rn(lo, hi);
    return *(uint32_t*)&h;
}

__global__ __launch_bounds__(THREADS)
void fused_attn(const int* __restrict__ qq, const int* __restrict__ qsh,
                const int* __restrict__ kq, const int* __restrict__ ksh,
                const int* __restrict__ vq, const int* __restrict__ vsh,
                float* __restrict__ out)
{
    extern __shared__ char sm[];
    float*         Ps  = (float*)sm;                                   // 32 x PS f32
    __nv_bfloat16* Qs  = (__nv_bfloat16*)(sm + SMEM_P_BYTES);          // 32 x QS
    __nv_bfloat16* Kv0 = (__nv_bfloat16*)(sm + SMEM_P_BYTES + SMEM_Q_BYTES);
    __nv_bfloat16* Kv1 = Kv0 + 128 * KS;

    const int bh   = blockIdx.y;
    const int t0   = blockIdx.x * QTILE;
    const int tid  = threadIdx.x;
    const int lane = tid & 31;
    const int wid  = tid >> 5;
    const int wm   = wid & 1;           // m-half (16 rows)
    const int wn   = wid >> 1;          // 0..7 (16-col slice)
    const int fr   = lane >> 2;         // fragment row 0..7
    const int fc   = (lane & 3) << 1;   // fragment col {0,2,4,6}

    // ldmatrix lane-dependent base addresses
    // A (Q tile): mat0 rows0-7 k0, mat1 rows8-15 k0, mat2 rows0-7 k8, mat3 rows8-15 k8
    const uint32_t aQ = smem_u32(&Qs[(wm * 16 + (lane & 15)) * QS + ((lane >> 4) << 3)]);
    // B (KV tile): mat0 nt0/k0, mat1 nt0/k8, mat2 nt1/k0, mat3 nt1/k8
    const uint32_t bKV0 = smem_u32(&Kv0[(wn * 16 + (lane & 7) + ((lane >> 4) << 3)) * KS
                                        + (((lane >> 3) & 1) << 3)]);
    const uint32_t bKV1 = bKV0 + SMEM_K_BYTES;

    // ---------------- load + dequant q tile (32 x 128) ----------------
    {
        const int* qb = qq  + ((size_t)bh * TD + t0) * HCD;
        const int* sb = qsh + ((size_t)bh * TD + t0) * (HCD / 8);
#pragma unroll
        for (int i = 0; i < 2; i++) {                      // 1024 int4 / 512 thr
            int u = tid + i * THREADS;
            int row = u >> 5, c4 = u & 31;
            int4 v = *(const int4*)(qb + (size_t)row * HCD + c4 * 4);
            int m = 1 << (sb[row * 16 + (c4 >> 1)] & 31);
            __nv_bfloat16 o[4];
            o[0] = __float2bfloat16_rn((float)(v.x * m));
            o[1] = __float2bfloat16_rn((float)(v.y * m));
            o[2] = __float2bfloat16_rn((float)(v.z * m));
            o[3] = __float2bfloat16_rn((float)(v.w * m));
            *(uint2*)&Qs[row * QS + c4 * 4] = *(const uint2*)o;
        }
    }

    // register prefetch state: 8 int4 + 8 scales per thread per chunk
    int4 pre[8];
    int  psh[8];

#define LOAD_K(CH)                                                        \
    {                                                                     \
        const int* kb_ = kq  + ((size_t)bh * SD + (CH) * 128) * HCD;      \
        const int* sb_ = ksh + ((size_t)bh * SD + (CH) * 128) * 16;       \
        _Pragma("unroll")                                                 \
        for (int i = 0; i < 8; i++) {                                     \
            int u = tid + i * THREADS;                                    \
            int row = u >> 5, c4 = u & 31;                                \
            pre[i] = *(const int4*)(kb_ + (size_t)row * HCD + c4 * 4);    \
            psh[i] = sb_[row * 16 + (c4 >> 1)];                           \
        }                                                                 \
    }

#define LOAD_V(CH)                                                        \
    {                                                                     \
        const int* vb_ = vq  + (size_t)bh * HCD * SD + (CH) * 128;        \
        const int* sb_ = vsh + (size_t)bh * HCD * (SD / 8) + (CH) * 16;   \
        _Pragma("unroll")                                                 \
        for (int i = 0; i < 8; i++) {                                     \
            int u = tid + i * THREADS;                                    \
            int row = u >> 5, s4 = u & 31;                                \
            pre[i] = *(const int4*)(vb_ + (size_t)row * SD + s4 * 4);     \
            psh[i] = sb_[row * (SD / 8) + (s4 >> 1)];                     \
        }                                                                 \
    }

#define STS_KV(BUF)                                                       \
    {                                                                     \
        _Pragma("unroll")                                                 \
        for (int i = 0; i < 8; i++) {                                     \
            int u = tid + i * THREADS;                                    \
            int row = u >> 5, c4 = u & 31;                                \
            int m = 1 << (psh[i] & 31);                                   \
            __nv_bfloat16 o[4];                                           \
            o[0] = __float2bfloat16_rn((float)(pre[i].x * m));            \
            o[1] = __float2bfloat16_rn((float)(pre[i].y * m));            \
            o[2] = __float2bfloat16_rn((float)(pre[i].z * m));            \
            o[3] = __float2bfloat16_rn((float)(pre[i].w * m));            \
            *(uint2*)&(BUF)[row * KS + c4 * 4] = *(const uint2*)o;        \
        }                                                                 \
    }

    // ---------------- QK: ping-pong double buffer ----------------------
    LOAD_K(0);
    STS_KV(Kv0);
    __syncthreads();

    for (int ch = 0; ch < NCH; ch++) {
        if (ch + 1 < NCH) LOAD_K(ch + 1);            // issue LDGs early
        const uint32_t bB = (ch & 1) ? bKV1 : bKV0;

        float acc[2][4];
#pragma unroll
        for (int nt = 0; nt < 2; nt++)
#pragma unroll
            for (int i = 0; i < 4; i++) acc[nt][i] = 0.f;

#pragma unroll
        for (int kk = 0; kk < 128; kk += 16) {
            uint32_t a[4], b[4];
            ldsm_x4(a, aQ + kk * 2);
            ldsm_x4(b, bB + kk * 2);
            mma16816(acc[0], a, b);
            mma16816(acc[1], a, b + 2);
        }
#pragma unroll
        for (int nt = 0; nt < 2; nt++) {
            int col = ch * 128 + wn * 16 + nt * 8 + fc;
            int r0 = (wm * 16 + fr) * PS;
            *(float2*)&Ps[r0 + col]          = make_float2(acc[nt][0], acc[nt][1]);
            *(float2*)&Ps[r0 + 8 * PS + col] = make_float2(acc[nt][2], acc[nt][3]);
        }
        if (ch + 1 < NCH) STS_KV((ch & 1) ? Kv0 : Kv1);
        __syncthreads();
    }

    // prefetch V chunk 0 — latency hides behind softmax
    LOAD_V(0);

    // ---------------- softmax + integer requant, in place in Ps --------
    // 16 threads per row; thread owns 8 whole groups-of-8: base (tr+16j)*8
    {
        const float SCALE = (float)(6.103515625e-05 / sqrt(128.0)); // f32(2^-14/sqrt(HC))
        const int srow = tid >> 4;      // 0..31
        const int tr   = tid & 15;
        float* P = Ps + srow * PS;

        float mx = -3.0e38f;
#pragma unroll
        for (int j = 0; j < 8; j++) {
            const float4* p4 = (const float4*)(P + (tr + 16 * j) * 8);
            float4 x0 = p4[0], x1 = p4[1];
            mx = fmaxf(mx, fmaxf(fmaxf(x0.x, x0.y), fmaxf(x0.z, x0.w)));
            mx = fmaxf(mx, fmaxf(fmaxf(x1.x, x1.y), fmaxf(x1.z, x1.w)));
        }
        mx = fmaxf(mx, __shfl_xor_sync(0xffffffffu, mx, 1));
        mx = fmaxf(mx, __shfl_xor_sync(0xffffffffu, mx, 2));
        mx = fmaxf(mx, __shfl_xor_sync(0xffffffffu, mx, 4));
        mx = fmaxf(mx, __shfl_xor_sync(0xffffffffu, mx, 8));
        const float lm = mx * SCALE;

        float sum = 0.f;
#pragma unroll
        for (int j = 0; j < 8; j++) {
            float4* p4 = (float4*)(P + (tr + 16 * j) * 8);
            float4 x0 = p4[0], x1 = p4[1];
            x0.x = expf(x0.x * SCALE - lm); x0.y = expf(x0.y * SCALE - lm);
            x0.z = expf(x0.z * SCALE - lm); x0.w = expf(x0.w * SCALE - lm);
            x1.x = expf(x1.x * SCALE - lm); x1.y = expf(x1.y * SCALE - lm);
            x1.z = expf(x1.z * SCALE - lm); x1.w = expf(x1.w * SCALE - lm);
            p4[0] = x0; p4[1] = x1;
            sum += ((x0.x + x0.y) + (x0.z + x0.w)) + ((x1.x + x1.y) + (x1.z + x1.w));
        }
        sum += __shfl_xor_sync(0xffffffffu, sum, 1);
        sum += __shfl_xor_sync(0xffffffffu, sum, 2);
        sum += __shfl_xor_sync(0xffffffffu, sum, 4);
        sum += __shfl_xor_sync(0xffffffffu, sum, 8);

#pragma unroll
        for (int j = 0; j < 8; j++) {
            float4* p4 = (float4*)(P + (tr + 16 * j) * 8);
            float4 x0 = p4[0], x1 = p4[1];
            float v[8];
            v[0] = rintf(__fdiv_rn(x0.x, sum) * 16384.0f);
            v[1] = rintf(__fdiv_rn(x0.y, sum) * 16384.0f);
            v[2] = rintf(__fdiv_rn(x0.z, sum) * 16384.0f);
            v[3] = rintf(__fdiv_rn(x0.w, sum) * 16384.0f);
            v[4] = rintf(__fdiv_rn(x1.x, sum) * 16384.0f);
            v[5] = rintf(__fdiv_rn(x1.y, sum) * 16384.0f);
            v[6] = rintf(__fdiv_rn(x1.z, sum) * 16384.0f);
            v[7] = rintf(__fdiv_rn(x1.w, sum) * 16384.0f);
            float g = fmaxf(fmaxf(fmaxf(v[0], v[1]), fmaxf(v[2], v[3])),
                            fmaxf(fmaxf(v[4], v[5]), fmaxf(v[6], v[7])));
            int gi = (int)g;                       // <= 16384
            int vv = (gi + 254) / 255;             // ceil(gi/255)
            int k  = (vv > 1) ? (32 - __clz(vv - 1)) : 0;   // clip(ceil(log2(g/255)),0)
            float dn = __int_as_float((127 - k) << 23);     // exact 2^-k
            float up = __int_as_float((127 + k) << 23);     // exact 2^k
            x0.x = fminf(rintf(v[0] * dn), 255.0f) * up;
            x0.y = fminf(rintf(v[1] * dn), 255.0f) * up;
            x0.z = fminf(rintf(v[2] * dn), 255.0f) * up;
            x0.w = fminf(rintf(v[3] * dn), 255.0f) * up;
            x1.x = fminf(rintf(v[4] * dn), 255.0f) * up;
            x1.y = fminf(rintf(v[5] * dn), 255.0f) * up;
            x1.z = fminf(rintf(v[6] * dn), 255.0f) * up;
            x1.w = fminf(rintf(v[7] * dn), 255.0f) * up;
            p4[0] = x0; p4[1] = x1;
        }
    }
    STS_KV(Kv0);
    __syncthreads();

    // ---------------- RV: ping-pong, r-frags from Ps -------------------
    float racc[2][4];
#pragma unroll
    for (int nt = 0; nt < 2; nt++)
#pragma unroll
        for (int i = 0; i < 4; i++) racc[nt][i] = 0.f;

    for (int ch = 0; ch < NCH; ch++) {
        if (ch + 1 < NCH) LOAD_V(ch + 1);
        const uint32_t bB = (ch & 1) ? bKV1 : bKV0;

#pragma unroll
        for (int kk = 0; kk < 128; kk += 16) {
            int r0 = (wm * 16 + fr) * PS + ch * 128 + kk + fc;
            float2 p00 = *(const float2*)&Ps[r0];
            float2 p10 = *(const float2*)&Ps[r0 + 8 * PS];
            float2 p01 = *(const float2*)&Ps[r0 + 8];
            float2 p11 = *(const float2*)&Ps[r0 + 8 * PS + 8];
            uint32_t a[4] = { f2bf2(p00.x, p00.y), f2bf2(p10.x, p10.y),
                              f2bf2(p01.x, p01.y), f2bf2(p11.x, p11.y) };
            uint32_t b[4];
            ldsm_x4(b, bB + kk * 2);
            mma16816(racc[0], a, b);
            mma16816(racc[1], a, b + 2);
        }
        if (ch + 1 < NCH) STS_KV((ch & 1) ? Kv0 : Kv1);
        __syncthreads();
    }

    // ---------------- epilogue: float32 output (rounded) ---------------
#pragma unroll
    for (int nt = 0; nt < 2; nt++) {
        int row = t0 + wm * 16 + fr;
        int col = wn * 16 + nt * 8 + fc;
        size_t base = (size_t)bh * TD * HCD;
        out[base + (size_t)row * HCD + col]           = rintf(racc[nt][0]);
        out[base + (size_t)row * HCD + col + 1]       = rintf(racc[nt][1]);
        out[base + (size_t)(row + 8) * HCD + col]     = rintf(racc[nt][2]);
        out[base + (size_t)(row + 8) * HCD + col + 1] = rintf(racc[nt][3]);
    }
}

// ---------------------------------------------------------------------------
static void diag_sync(const char* stage)
{
    cudaStreamCaptureStatus st = cudaStreamCaptureStatusNone;
    cudaStreamIsCapturing(0, &st);
    if (st == cudaStreamCaptureStatusNone) {
        cudaError_t e = cudaStreamSynchronize(0);
        if (e != cudaSuccess)
            fprintf(stderr, "[kl] stage %s: %s\n", stage, cudaGetErrorString(e));
    }
}

extern "C" void kernel_launch(void* const* d_in, const int* in_sizes, int n_in,
                              void* d_out, int out_size)
{
    if (n_in < 6) { fprintf(stderr, "[kl] bad n_in=%d\n", n_in); return; }

    const int* qq  = (const int*)d_in[0];
    const int* qsh = (const int*)d_in[1];
    const int* kq  = (const int*)d_in[2];
    const int* ksh = (const int*)d_in[3];
    const int* vq  = (const int*)d_in[4];
    const int* vsh = (const int*)d_in[5];

    cudaError_t e = cudaFuncSetAttribute(fused_attn,
        cudaFuncAttributeMaxDynamicSharedMemorySize, SMEM_TOTAL);
    if (e != cudaSuccess)
        fprintf(stderr, "[kl] attr: %s\n", cudaGetErrorString(e));

    dim3 grid(TD / QTILE, BHN);     // 32 x 32
    fused_attn<<<grid, THREADS, SMEM_TOTAL>>>(qq, qsh, kq, ksh, vq, vsh,
                                              (float*)d_out);
    diag_sync("fused_attn");
}

// round 11
// speedup vs baseline: 1.8022x; 1.2052x over previous
#include <cuda_runtime.h>
#include <cuda_bf16.h>
#include <math.h>
#include <stdio.h>
#include <stdint.h>

// Dims
#define BHN 32
#define TD 1024
#define SD 1024
#define HCD 128
#define QTILE 32           // q rows per CTA
#define NCH 8              // S chunks of 128
#define THREADS 512        // 16 warps

// smem strides (elements)
#define QS 136             // q tile row stride, bf16
#define KS 136             // k/vt tile row stride, bf16
#define PS 1036            // score row stride, f32
#define RBS 524            // r tile row stride, u32 (=2096B; 2096%128=48 -> ldsm conflict-free)

#define SMEM_P_BYTES  (QTILE * PS * 4)            // 132,608
#define SMEM_Q_BYTES  (QTILE * QS * 2)            //   8,704
#define SMEM_K_BYTES  (128 * KS * 2)              //  34,816 per buffer
#define SMEM_TOTAL    (SMEM_P_BYTES + SMEM_Q_BYTES + 2 * SMEM_K_BYTES) // 210,944

__device__ __forceinline__ void mma16816(float c[4], const uint32_t a[4], const uint32_t b[2])
{
    asm volatile(
        "mma.sync.aligned.m16n8k16.row.col.f32.bf16.bf16.f32 "
        "{%0,%1,%2,%3}, {%4,%5,%6,%7}, {%8,%9}, {%0,%1,%2,%3};\n"
        : "+f"(c[0]), "+f"(c[1]), "+f"(c[2]), "+f"(c[3])
        : "r"(a[0]), "r"(a[1]), "r"(a[2]), "r"(a[3]), "r"(b[0]), "r"(b[1]));
}

__device__ __forceinline__ void ldsm_x4(uint32_t r[4], uint32_t addr)
{
    asm volatile("ldmatrix.sync.aligned.m8n8.x4.shared.b16 {%0,%1,%2,%3}, [%4];"
                 : "=r"(r[0]), "=r"(r[1]), "=r"(r[2]), "=r"(r[3]) : "r"(addr));
}

__device__ __forceinline__ uint32_t smem_u32(const void* p)
{
    return (uint32_t)__cvta_generic_to_shared(p);
}

__device__ __forceinline__ uint32_t f2bf2(float lo, float hi)
{
    __nv_bfloat162 h = __floats2bfloat162_rn(lo, hi);
    return *(uint32_t*)&h;
}

__global__ __launch_bounds__(THREADS)
void fused_attn(const int* __restrict__ qq, const int* __restrict__ qsh,
                const int* __restrict__ kq, const int* __restrict__ ksh,
                const int* __restrict__ vq, const int* __restrict__ vsh,
                float* __restrict__ out)
{
    extern __shared__ char sm[];
    float*         Ps  = (float*)sm;                                   // 32 x PS f32
    uint32_t*      Rb  = (uint32_t*)sm;                                // 32 x RBS u32 (aliases Ps; live after requant)
    __nv_bfloat16* Qs  = (__nv_bfloat16*)(sm + SMEM_P_BYTES);          // 32 x QS
    __nv_bfloat16* Kv0 = (__nv_bfloat16*)(sm + SMEM_P_BYTES + SMEM_Q_BYTES);
    __nv_bfloat16* Kv1 = Kv0 + 128 * KS;

    const int bh   = blockIdx.y;
    const int t0   = blockIdx.x * QTILE;
    const int tid  = threadIdx.x;
    const int lane = tid & 31;
    const int wid  = tid >> 5;
    const int wm   = wid & 1;           // m-half (16 rows)
    const int wn   = wid >> 1;          // 0..7 (16-col slice)
    const int fr   = lane >> 2;         // fragment row 0..7
    const int fc   = (lane & 3) << 1;   // fragment col {0,2,4,6}

    // ldmatrix lane-dependent base addresses
    const uint32_t aQ = smem_u32(&Qs[(wm * 16 + (lane & 15)) * QS + ((lane >> 4) << 3)]);
    const uint32_t bKV0 = smem_u32(&Kv0[(wn * 16 + (lane & 7) + ((lane >> 4) << 3)) * KS
                                        + (((lane >> 3) & 1) << 3)]);
    const uint32_t bKV1 = bKV0 + SMEM_K_BYTES;
    // r tile (bf16) A-fragment base: row wm*16+(lane&15), k-byte (lane>>4)*16
    const uint32_t aR = smem_u32(Rb) + (wm * 16 + (lane & 15)) * (RBS * 4)
                        + ((lane >> 4) << 4);

    // ---------------- load + dequant q tile (32 x 128) ----------------
    {
        const int* qb = qq  + ((size_t)bh * TD + t0) * HCD;
        const int* sb = qsh + ((size_t)bh * TD + t0) * (HCD / 8);
#pragma unroll
        for (int i = 0; i < 2; i++) {                      // 1024 int4 / 512 thr
            int u = tid + i * THREADS;
            int row = u >> 5, c4 = u & 31;
            int4 v = *(const int4*)(qb + (size_t)row * HCD + c4 * 4);
            int m = 1 << (sb[row * 16 + (c4 >> 1)] & 31);
            __nv_bfloat16 o[4];
            o[0] = __float2bfloat16_rn((float)(v.x * m));
            o[1] = __float2bfloat16_rn((float)(v.y * m));
            o[2] = __float2bfloat16_rn((float)(v.z * m));
            o[3] = __float2bfloat16_rn((float)(v.w * m));
            *(uint2*)&Qs[row * QS + c4 * 4] = *(const uint2*)o;
        }
    }

    // register prefetch state: 8 int4 + 8 scales per thread per chunk
    int4 pre[8];
    int  psh[8];

#define LOAD_K(CH)                                                        \
    {                                                                     \
        const int* kb_ = kq  + ((size_t)bh * SD + (CH) * 128) * HCD;      \
        const int* sb_ = ksh + ((size_t)bh * SD + (CH) * 128) * 16;       \
        _Pragma("unroll")                                                 \
        for (int i = 0; i < 8; i++) {                                     \
            int u = tid + i * THREADS;                                    \
            int row = u >> 5, c4 = u & 31;                                \
            pre[i] = *(const int4*)(kb_ + (size_t)row * HCD + c4 * 4);    \
            psh[i] = sb_[row * 16 + (c4 >> 1)];                           \
        }                                                                 \
    }

#define LOAD_V(CH)                                                        \
    {                                                                     \
        const int* vb_ = vq  + (size_t)bh * HCD * SD + (CH) * 128;        \
        const int* sb_ = vsh + (size_t)bh * HCD * (SD / 8) + (CH) * 16;   \
        _Pragma("unroll")                                                 \
        for (int i = 0; i < 8; i++) {                                     \
            int u = tid + i * THREADS;                                    \
            int row = u >> 5, s4 = u & 31;                                \
            pre[i] = *(const int4*)(vb_ + (size_t)row * SD + s4 * 4);     \
            psh[i] = sb_[row * (SD / 8) + (s4 >> 1)];                     \
        }                                                                 \
    }

#define STS_KV(BUF)                                                       \
    {                                                                     \
        _Pragma("unroll")                                                 \
        for (int i = 0; i < 8; i++) {                                     \
            int u = tid + i * THREADS;                                    \
            int row = u >> 5, c4 = u & 31;                                \
            int m = 1 << (psh[i] & 31);                                   \
            __nv_bfloat16 o[4];                                           \
            o[0] = __float2bfloat16_rn((float)(pre[i].x * m));            \
            o[1] = __float2bfloat16_rn((float)(pre[i].y * m));            \
            o[2] = __float2bfloat16_rn((float)(pre[i].z * m));            \
            o[3] = __float2bfloat16_rn((float)(pre[i].w * m));            \
            *(uint2*)&(BUF)[row * KS + c4 * 4] = *(const uint2*)o;        \
        }                                                                 \
    }

    // ---------------- QK: ping-pong double buffer ----------------------
    LOAD_K(0);
    STS_KV(Kv0);
    __syncthreads();

    // Q A-fragments hoisted to registers (Q is reused by all 16 chunks)
    uint32_t afq[8][4];
#pragma unroll
    for (int ks = 0; ks < 8; ks++) ldsm_x4(afq[ks], aQ + ks * 32);

    for (int ch = 0; ch < NCH; ch++) {
        if (ch + 1 < NCH) LOAD_K(ch + 1);            // issue LDGs early
        const uint32_t bB = (ch & 1) ? bKV1 : bKV0;

        float acc[2][4];
#pragma unroll
        for (int nt = 0; nt < 2; nt++)
#pragma unroll
            for (int i = 0; i < 4; i++) acc[nt][i] = 0.f;

#pragma unroll
        for (int ks = 0; ks < 8; ks++) {
            uint32_t b[4];
            ldsm_x4(b, bB + ks * 32);
            mma16816(acc[0], afq[ks], b);
            mma16816(acc[1], afq[ks], b + 2);
        }
#pragma unroll
        for (int nt = 0; nt < 2; nt++) {
            int col = ch * 128 + wn * 16 + nt * 8 + fc;
            int r0 = (wm * 16 + fr) * PS;
            *(float2*)&Ps[r0 + col]          = make_float2(acc[nt][0], acc[nt][1]);
            *(float2*)&Ps[r0 + 8 * PS + col] = make_float2(acc[nt][2], acc[nt][3]);
        }
        if (ch + 1 < NCH) STS_KV((ch & 1) ? Kv0 : Kv1);
        __syncthreads();
    }

    // ---------------- softmax + integer requant: Ps f32 -> Rb bf16 -----
    // 16 threads per row; thread owns 8 whole groups-of-8 (cols (tr+16j)*8..+8)
    {
        const float SCALE = (float)(6.103515625e-05 / sqrt(128.0)); // f32(2^-14/sqrt(HC))
        const int srow = tid >> 4;      // 0..31
        const int tr   = tid & 15;
        float* P = Ps + srow * PS;

        float mx = -3.0e38f;
#pragma unroll
        for (int j = 0; j < 8; j++) {
            const float4* p4 = (const float4*)(P + (tr + 16 * j) * 8);
            float4 x0 = p4[0], x1 = p4[1];
            mx = fmaxf(mx, fmaxf(fmaxf(x0.x, x0.y), fmaxf(x0.z, x0.w)));
            mx = fmaxf(mx, fmaxf(fmaxf(x1.x, x1.y), fmaxf(x1.z, x1.w)));
        }
        mx = fmaxf(mx, __shfl_xor_sync(0xffffffffu, mx, 1));
        mx = fmaxf(mx, __shfl_xor_sync(0xffffffffu, mx, 2));
        mx = fmaxf(mx, __shfl_xor_sync(0xffffffffu, mx, 4));
        mx = fmaxf(mx, __shfl_xor_sync(0xffffffffu, mx, 8));
        const float lm = mx * SCALE;

        float sum = 0.f;
#pragma unroll
        for (int j = 0; j < 8; j++) {
            float4* p4 = (float4*)(P + (tr + 16 * j) * 8);
            float4 x0 = p4[0], x1 = p4[1];
            x0.x = expf(x0.x * SCALE - lm); x0.y = expf(x0.y * SCALE - lm);
            x0.z = expf(x0.z * SCALE - lm); x0.w = expf(x0.w * SCALE - lm);
            x1.x = expf(x1.x * SCALE - lm); x1.y = expf(x1.y * SCALE - lm);
            x1.z = expf(x1.z * SCALE - lm); x1.w = expf(x1.w * SCALE - lm);
            p4[0] = x0; p4[1] = x1;
            sum += ((x0.x + x0.y) + (x0.z + x0.w)) + ((x1.x + x1.y) + (x1.z + x1.w));
        }
        sum += __shfl_xor_sync(0xffffffffu, sum, 1);
        sum += __shfl_xor_sync(0xffffffffu, sum, 2);
        sum += __shfl_xor_sync(0xffffffffu, sum, 4);
        sum += __shfl_xor_sync(0xffffffffu, sum, 8);

        // prefetch V chunk 0 now — latency hides behind requant
        LOAD_V(0);

        // requant -> bf16 pairs staged in regs (Ps reads finish before Rb writes)
        uint4 stash[8];
#pragma unroll
        for (int j = 0; j < 8; j++) {
            const float4* p4 = (const float4*)(P + (tr + 16 * j) * 8);
            float4 x0 = p4[0], x1 = p4[1];
            float v[8];
            v[0] = rintf(__fdiv_rn(x0.x, sum) * 16384.0f);
            v[1] = rintf(__fdiv_rn(x0.y, sum) * 16384.0f);
            v[2] = rintf(__fdiv_rn(x0.z, sum) * 16384.0f);
            v[3] = rintf(__fdiv_rn(x0.w, sum) * 16384.0f);
            v[4] = rintf(__fdiv_rn(x1.x, sum) * 16384.0f);
            v[5] = rintf(__fdiv_rn(x1.y, sum) * 16384.0f);
            v[6] = rintf(__fdiv_rn(x1.z, sum) * 16384.0f);
            v[7] = rintf(__fdiv_rn(x1.w, sum) * 16384.0f);
            float g = fmaxf(fmaxf(fmaxf(v[0], v[1]), fmaxf(v[2], v[3])),
                            fmaxf(fmaxf(v[4], v[5]), fmaxf(v[6], v[7])));
            int gi = (int)g;                       // <= 16384
            int vv = (gi + 254) / 255;             // ceil(gi/255)
            int k  = (vv > 1) ? (32 - __clz(vv - 1)) : 0;   // clip(ceil(log2(g/255)),0)
            float dn = __int_as_float((127 - k) << 23);     // exact 2^-k
            float up = __int_as_float((127 + k) << 23);     // exact 2^k
            float r0 = fminf(rintf(v[0] * dn), 255.0f) * up;
            float r1 = fminf(rintf(v[1] * dn), 255.0f) * up;
            float r2 = fminf(rintf(v[2] * dn), 255.0f) * up;
            float r3 = fminf(rintf(v[3] * dn), 255.0f) * up;
            float r4 = fminf(rintf(v[4] * dn), 255.0f) * up;
            float r5 = fminf(rintf(v[5] * dn), 255.0f) * up;
            float r6 = fminf(rintf(v[6] * dn), 255.0f) * up;
            float r7 = fminf(rintf(v[7] * dn), 255.0f) * up;
            stash[j].x = f2bf2(r0, r1);            // exact: <=8-bit mantissa * po2
            stash[j].y = f2bf2(r2, r3);
            stash[j].z = f2bf2(r4, r5);
            stash[j].w = f2bf2(r6, r7);
        }
        __syncthreads();                           // all Ps f32 reads done
#pragma unroll
        for (int j = 0; j < 8; j++)
            *(uint4*)&Rb[srow * RBS + (tr + 16 * j) * 4] = stash[j];
    }
    STS_KV(Kv0);
    __syncthreads();

    // ---------------- RV: ping-pong, A-frags via ldmatrix from Rb ------
    float racc[2][4];
#pragma unroll
    for (int nt = 0; nt < 2; nt++)
#pragma unroll
        for (int i = 0; i < 4; i++) racc[nt][i] = 0.f;

    for (int ch = 0; ch < NCH; ch++) {
        if (ch + 1 < NCH) LOAD_V(ch + 1);
        const uint32_t bB = (ch & 1) ? bKV1 : bKV0;

#pragma unroll
        for (int ks = 0; ks < 8; ks++) {
            uint32_t a[4], b[4];
            ldsm_x4(a, aR + (ch * 128 + ks * 16) * 2);
            ldsm_x4(b, bB + ks * 32);
            mma16816(racc[0], a, b);
            mma16816(racc[1], a, b + 2);
        }
        if (ch + 1 < NCH) STS_KV((ch & 1) ? Kv0 : Kv1);
        __syncthreads();
    }

    // ---------------- epilogue: float32 output (rounded) ---------------
#pragma unroll
    for (int nt = 0; nt < 2; nt++) {
        int row = t0 + wm * 16 + fr;
        int col = wn * 16 + nt * 8 + fc;
        size_t base = (size_t)bh * TD * HCD;
        out[base + (size_t)row * HCD + col]           = rintf(racc[nt][0]);
        out[base + (size_t)row * HCD + col + 1]       = rintf(racc[nt][1]);
        out[base + (size_t)(row + 8) * HCD + col]     = rintf(racc[nt][2]);
        out[base + (size_t)(row + 8) * HCD + col + 1] = rintf(racc[nt][3]);
    }
}

// ---------------------------------------------------------------------------
static void diag_sync(const char* stage)
{
    cudaStreamCaptureStatus st = cudaStreamCaptureStatusNone;
    cudaStreamIsCapturing(0, &st);
    if (st == cudaStreamCaptureStatusNone) {
        cudaError_t e = cudaStreamSynchronize(0);
        if (e != cudaSuccess)
            fprintf(stderr, "[kl] stage %s: %s\n", stage, cudaGetErrorString(e));
    }
}

extern "C" void kernel_launch(void* const* d_in, const int* in_sizes, int n_in,
                              void* d_out, int out_size)
{
    if (n_in < 6) { fprintf(stderr, "[kl] bad n_in=%d\n", n_in); return; }

    const int* qq  = (const int*)d_in[0];
    const int* qsh = (const int*)d_in[1];
    const int* kq  = (const int*)d_in[2];
    const int* ksh = (const int*)d_in[3];
    const int* vq  = (const int*)d_in[4];
    const int* vsh = (const int*)d_in[5];

    cudaError_t e = cudaFuncSetAttribute(fused_attn,
        cudaFuncAttributeMaxDynamicSharedMemorySize, SMEM_TOTAL);
    if (e != cudaSuccess)
        fprintf(stderr, "[kl] attr: %s\n", cudaGetErrorString(e));

    dim3 grid(TD / QTILE, BHN);     // 32 x 32
    fused_attn<<<grid, THREADS, SMEM_TOTAL>>>(qq, qsh, kq, ksh, vq, vsh,
                                              (float*)d_out);
    diag_sync("fused_attn");
}

// round 12
// speedup vs baseline: 2.4199x; 1.3428x over previous
#include <cuda_runtime.h>
#include <cuda_bf16.h>
#include <math.h>
#include <stdio.h>
#include <stdint.h>

// Dims
#define BHN 32
#define TD 1024
#define SD 1024
#define HCD 128
#define QTILE 32           // q rows per CTA
#define NCH 8              // S chunks of 128
#define THREADS 512        // 16 warps
#define N_ELEM (BHN * TD * HCD)

// smem strides (elements)
#define QS 136             // q tile row stride, bf16
#define KS 136             // k/vt tile row stride, bf16
#define PS 1036            // score row stride, f32
#define RBS 524            // r tile row stride, u32 (=2096B; phase walk 48 -> ldsm conflict-free)

#define SMEM_P_BYTES  (QTILE * PS * 4)            // 132,608
#define SMEM_Q_BYTES  (QTILE * QS * 2)            //   8,704
#define SMEM_K_BYTES  (128 * KS * 2)              //  34,816 per buffer
#define SMEM_TOTAL    (SMEM_P_BYTES + SMEM_Q_BYTES + 2 * SMEM_K_BYTES) // 210,944

// ------------- bf16 scratch (device globals; allowed for scratch) ----------
__device__ __align__(128) __nv_bfloat16 g_qb[N_ELEM];    // [bh][t][c]
__device__ __align__(128) __nv_bfloat16 g_kb[N_ELEM];    // [bh][s][c]
__device__ __align__(128) __nv_bfloat16 g_vtb[N_ELEM];   // [bh][c][s]

// ---------------- pre-pass dequant: (q << s) exact in bf16 -----------------
// Last axis is the grouped one for all three tensors -> flat mapping i>>3.
template <int DST>
__global__ __launch_bounds__(256)
void dequant4(const int* __restrict__ q, const int* __restrict__ s)
{
    __nv_bfloat16* out = (DST == 0) ? g_qb : (DST == 1) ? g_kb : g_vtb;
    int i = blockIdx.x * 256 + threadIdx.x;            // int4 index (exact grid)
    int4 v = ((const int4*)q)[i];
    int m = 1 << (s[i >> 1] & 31);
    __nv_bfloat16 o[4];
    o[0] = __float2bfloat16_rn((float)(v.x * m));
    o[1] = __float2bfloat16_rn((float)(v.y * m));
    o[2] = __float2bfloat16_rn((float)(v.z * m));
    o[3] = __float2bfloat16_rn((float)(v.w * m));
    ((uint2*)out)[i] = *(const uint2*)o;
}

__device__ __forceinline__ void mma16816(float c[4], const uint32_t a[4], const uint32_t b[2])
{
    asm volatile(
        "mma.sync.aligned.m16n8k16.row.col.f32.bf16.bf16.f32 "
        "{%0,%1,%2,%3}, {%4,%5,%6,%7}, {%8,%9}, {%0,%1,%2,%3};\n"
        : "+f"(c[0]), "+f"(c[1]), "+f"(c[2]), "+f"(c[3])
        : "r"(a[0]), "r"(a[1]), "r"(a[2]), "r"(a[3]), "r"(b[0]), "r"(b[1]));
}

__device__ __forceinline__ void ldsm_x4(uint32_t r[4], uint32_t addr)
{
    asm volatile("ldmatrix.sync.aligned.m8n8.x4.shared.b16 {%0,%1,%2,%3}, [%4];"
                 : "=r"(r[0]), "=r"(r[1]), "=r"(r[2]), "=r"(r[3]) : "r"(addr));
}

__device__ __forceinline__ uint32_t smem_u32(const void* p)
{
    return (uint32_t)__cvta_generic_to_shared(p);
}

__device__ __forceinline__ uint32_t f2bf2(float lo, float hi)
{
    __nv_bfloat162 h = __floats2bfloat162_rn(lo, hi);
    return *(uint32_t*)&h;
}

__global__ __launch_bounds__(THREADS)
void fused_attn(float* __restrict__ out)
{
    extern __shared__ char sm[];
    float*         Ps  = (float*)sm;                                   // 32 x PS f32
    uint32_t*      Rb  = (uint32_t*)sm;                                // aliases Ps after requant
    __nv_bfloat16* Qs  = (__nv_bfloat16*)(sm + SMEM_P_BYTES);          // 32 x QS
    __nv_bfloat16* Kv0 = (__nv_bfloat16*)(sm + SMEM_P_BYTES + SMEM_Q_BYTES);
    __nv_bfloat16* Kv1 = Kv0 + 128 * KS;

    const int bh   = blockIdx.y;
    const int t0   = blockIdx.x * QTILE;
    const int tid  = threadIdx.x;
    const int lane = tid & 31;
    const int wid  = tid >> 5;
    const int wm   = wid & 1;           // m-half (16 rows)
    const int wn   = wid >> 1;          // 0..7 (16-col slice)
    const int fr   = lane >> 2;         // fragment row 0..7
    const int fc   = (lane & 3) << 1;   // fragment col {0,2,4,6}

    // ldmatrix lane-dependent base addresses
    const uint32_t aQ = smem_u32(&Qs[(wm * 16 + (lane & 15)) * QS + ((lane >> 4) << 3)]);
    const uint32_t bKV0 = smem_u32(&Kv0[(wn * 16 + (lane & 7) + ((lane >> 4) << 3)) * KS
                                        + (((lane >> 3) & 1) << 3)]);
    const uint32_t bKV1 = bKV0 + SMEM_K_BYTES;
    const uint32_t aR = smem_u32(Rb) + (wm * 16 + (lane & 15)) * (RBS * 4)
                        + ((lane >> 4) << 4);

    // copy indices: 16 uint4 per 128-bf16 row
    const int crow = tid >> 4;          // 0..31 (Q) / +128 steps (KV)
    const int cseg = tid & 15;          // 0..15

    // ---------------- Q tile copy (32 x 128 bf16 = 512 uint4) ---------
    {
        const uint4* src = (const uint4*)(g_qb + ((size_t)bh * TD + t0) * HCD);
        *(uint4*)&Qs[crow * QS + cseg * 8] = src[crow * 16 + cseg];
    }

    // register prefetch: 4 uint4 per thread per chunk
    uint4 pre4[4];

#define LOAD_K(CH)                                                         \
    {                                                                      \
        const uint4* src = (const uint4*)(g_kb + ((size_t)bh * SD + (CH) * 128) * HCD); \
        _Pragma("unroll")                                                  \
        for (int i = 0; i < 4; i++) {                                      \
            int u = tid + i * THREADS;                                     \
            pre4[i] = src[u];                                              \
        }                                                                  \
    }

    // VT chunk: rows are channels c (stride SD), cols are s in [CH*128, CH*128+128)
#define LOAD_V(CH)                                                         \
    {                                                                      \
        const __nv_bfloat16* src = g_vtb + (size_t)bh * HCD * SD + (CH) * 128; \
        _Pragma("unroll")                                                  \
        for (int i = 0; i < 4; i++) {                                      \
            int u = tid + i * THREADS;                                     \
            int row = u >> 4, seg = u & 15;                                \
            pre4[i] = *(const uint4*)(src + (size_t)row * SD + seg * 8);   \
        }                                                                  \
    }

#define STS_KV(BUF)                                                        \
    {                                                                      \
        _Pragma("unroll")                                                  \
        for (int i = 0; i < 4; i++) {                                      \
            int u = tid + i * THREADS;                                     \
            int row = u >> 4, seg = u & 15;                                \
            *(uint4*)&(BUF)[row * KS + seg * 8] = pre4[i];                 \
        }                                                                  \
    }

    // ---------------- QK: ping-pong double buffer ----------------------
    LOAD_K(0);
    STS_KV(Kv0);
    __syncthreads();

    // Q A-fragments hoisted to registers
    uint32_t afq[8][4];
#pragma unroll
    for (int ks = 0; ks < 8; ks++) ldsm_x4(afq[ks], aQ + ks * 32);

    for (int ch = 0; ch < NCH; ch++) {
        if (ch + 1 < NCH) LOAD_K(ch + 1);            // issue LDGs early
        const uint32_t bB = (ch & 1) ? bKV1 : bKV0;

        float acc[2][4];
#pragma unroll
        for (int nt = 0; nt < 2; nt++)
#pragma unroll
            for (int i = 0; i < 4; i++) acc[nt][i] = 0.f;

#pragma unroll
        for (int ks = 0; ks < 8; ks++) {
            uint32_t b[4];
            ldsm_x4(b, bB + ks * 32);
            mma16816(acc[0], afq[ks], b);
            mma16816(acc[1], afq[ks], b + 2);
        }
#pragma unroll
        for (int nt = 0; nt < 2; nt++) {
            int col = ch * 128 + wn * 16 + nt * 8 + fc;
            int r0 = (wm * 16 + fr) * PS;
            *(float2*)&Ps[r0 + col]          = make_float2(acc[nt][0], acc[nt][1]);
            *(float2*)&Ps[r0 + 8 * PS + col] = make_float2(acc[nt][2], acc[nt][3]);
        }
        if (ch + 1 < NCH) STS_KV((ch & 1) ? Kv0 : Kv1);
        __syncthreads();
    }

    // ---------------- softmax + integer requant: Ps f32 -> Rb bf16 -----
    {
        const float SCALE = (float)(6.103515625e-05 / sqrt(128.0)); // f32(2^-14/sqrt(HC))
        const int srow = tid >> 4;      // 0..31
        const int tr   = tid & 15;
        float* P = Ps + srow * PS;

        float mx = -3.0e38f;
#pragma unroll
        for (int j = 0; j < 8; j++) {
            const float4* p4 = (const float4*)(P + (tr + 16 * j) * 8);
            float4 x0 = p4[0], x1 = p4[1];
            mx = fmaxf(mx, fmaxf(fmaxf(x0.x, x0.y), fmaxf(x0.z, x0.w)));
            mx = fmaxf(mx, fmaxf(fmaxf(x1.x, x1.y), fmaxf(x1.z, x1.w)));
        }
        mx = fmaxf(mx, __shfl_xor_sync(0xffffffffu, mx, 1));
        mx = fmaxf(mx, __shfl_xor_sync(0xffffffffu, mx, 2));
        mx = fmaxf(mx, __shfl_xor_sync(0xffffffffu, mx, 4));
        mx = fmaxf(mx, __shfl_xor_sync(0xffffffffu, mx, 8));
        const float lm = mx * SCALE;

        float sum = 0.f;
#pragma unroll
        for (int j = 0; j < 8; j++) {
            float4* p4 = (float4*)(P + (tr + 16 * j) * 8);
            float4 x0 = p4[0], x1 = p4[1];
            x0.x = expf(x0.x * SCALE - lm); x0.y = expf(x0.y * SCALE - lm);
            x0.z = expf(x0.z * SCALE - lm); x0.w = expf(x0.w * SCALE - lm);
            x1.x = expf(x1.x * SCALE - lm); x1.y = expf(x1.y * SCALE - lm);
            x1.z = expf(x1.z * SCALE - lm); x1.w = expf(x1.w * SCALE - lm);
            p4[0] = x0; p4[1] = x1;
            sum += ((x0.x + x0.y) + (x0.z + x0.w)) + ((x1.x + x1.y) + (x1.z + x1.w));
        }
        sum += __shfl_xor_sync(0xffffffffu, sum, 1);
        sum += __shfl_xor_sync(0xffffffffu, sum, 2);
        sum += __shfl_xor_sync(0xffffffffu, sum, 4);
        sum += __shfl_xor_sync(0xffffffffu, sum, 8);

        // prefetch V chunk 0 now — latency hides behind requant
        LOAD_V(0);

        uint4 stash[8];
#pragma unroll
        for (int j = 0; j < 8; j++) {
            const float4* p4 = (const float4*)(P + (tr + 16 * j) * 8);
            float4 x0 = p4[0], x1 = p4[1];
            float v[8];
            v[0] = rintf(__fdiv_rn(x0.x, sum) * 16384.0f);
            v[1] = rintf(__fdiv_rn(x0.y, sum) * 16384.0f);
            v[2] = rintf(__fdiv_rn(x0.z, sum) * 16384.0f);
            v[3] = rintf(__fdiv_rn(x0.w, sum) * 16384.0f);
            v[4] = rintf(__fdiv_rn(x1.x, sum) * 16384.0f);
            v[5] = rintf(__fdiv_rn(x1.y, sum) * 16384.0f);
            v[6] = rintf(__fdiv_rn(x1.z, sum) * 16384.0f);
            v[7] = rintf(__fdiv_rn(x1.w, sum) * 16384.0f);
            float g = fmaxf(fmaxf(fmaxf(v[0], v[1]), fmaxf(v[2], v[3])),
                            fmaxf(fmaxf(v[4], v[5]), fmaxf(v[6], v[7])));
            int gi = (int)g;                       // <= 16384
            int vv = (gi + 254) / 255;             // ceil(gi/255)
            int k  = (vv > 1) ? (32 - __clz(vv - 1)) : 0;   // clip(ceil(log2(g/255)),0)
            float dn = __int_as_float((127 - k) << 23);     // exact 2^-k
            float up = __int_as_float((127 + k) << 23);     // exact 2^k
            float r0 = fminf(rintf(v[0] * dn), 255.0f) * up;
            float r1 = fminf(rintf(v[1] * dn), 255.0f) * up;
            float r2 = fminf(rintf(v[2] * dn), 255.0f) * up;
            float r3 = fminf(rintf(v[3] * dn), 255.0f) * up;
            float r4 = fminf(rintf(v[4] * dn), 255.0f) * up;
            float r5 = fminf(rintf(v[5] * dn), 255.0f) * up;
            float r6 = fminf(rintf(v[6] * dn), 255.0f) * up;
            float r7 = fminf(rintf(v[7] * dn), 255.0f) * up;
            stash[j].x = f2bf2(r0, r1);            // exact: <=8-bit mantissa * po2
            stash[j].y = f2bf2(r2, r3);
            stash[j].z = f2bf2(r4, r5);
            stash[j].w = f2bf2(r6, r7);
        }
        __syncthreads();                           // all Ps f32 reads done
#pragma unroll
        for (int j = 0; j < 8; j++)
            *(uint4*)&Rb[srow * RBS + (tr + 16 * j) * 4] = stash[j];
    }
    STS_KV(Kv0);
    __syncthreads();

    // ---------------- RV: ping-pong, A-frags via ldmatrix from Rb ------
    float racc[2][4];
#pragma unroll
    for (int nt = 0; nt < 2; nt++)
#pragma unroll
        for (int i = 0; i < 4; i++) racc[nt][i] = 0.f;

    for (int ch = 0; ch < NCH; ch++) {
        if (ch + 1 < NCH) LOAD_V(ch + 1);
        const uint32_t bB = (ch & 1) ? bKV1 : bKV0;

#pragma unroll
        for (int ks = 0; ks < 8; ks++) {
            uint32_t a[4], b[4];
            ldsm_x4(a, aR + (ch * 128 + ks * 16) * 2);
            ldsm_x4(b, bB + ks * 32);
            mma16816(racc[0], a, b);
            mma16816(racc[1], a, b + 2);
        }
        if (ch + 1 < NCH) STS_KV((ch & 1) ? Kv0 : Kv1);
        __syncthreads();
    }

    // ---------------- epilogue: float32 output (rounded) ---------------
#pragma unroll
    for (int nt = 0; nt < 2; nt++) {
        int row = t0 + wm * 16 + fr;
        int col = wn * 16 + nt * 8 + fc;
        size_t base = (size_t)bh * TD * HCD;
        out[base + (size_t)row * HCD + col]           = rintf(racc[nt][0]);
        out[base + (size_t)row * HCD + col + 1]       = rintf(racc[nt][1]);
        out[base + (size_t)(row + 8) * HCD + col]     = rintf(racc[nt][2]);
        out[base + (size_t)(row + 8) * HCD + col + 1] = rintf(racc[nt][3]);
    }
}

// ---------------------------------------------------------------------------
static void diag_sync(const char* stage)
{
    cudaStreamCaptureStatus st = cudaStreamCaptureStatusNone;
    cudaStreamIsCapturing(0, &st);
    if (st == cudaStreamCaptureStatusNone) {
        cudaError_t e = cudaStreamSynchronize(0);
        if (e != cudaSuccess)
            fprintf(stderr, "[kl] stage %s: %s\n", stage, cudaGetErrorString(e));
    }
}

extern "C" void kernel_launch(void* const* d_in, const int* in_sizes, int n_in,
                              void* d_out, int out_size)
{
    if (n_in < 6) { fprintf(stderr, "[kl] bad n_in=%d\n", n_in); return; }

    const int* qq  = (const int*)d_in[0];
    const int* qsh = (const int*)d_in[1];
    const int* kq  = (const int*)d_in[2];
    const int* ksh = (const int*)d_in[3];
    const int* vq  = (const int*)d_in[4];
    const int* vsh = (const int*)d_in[5];

    const int blk = N_ELEM / 4 / 256;               // 4096, exact
    dequant4<0><<<blk, 256>>>(qq, qsh);
    dequant4<1><<<blk, 256>>>(kq, ksh);
    dequant4<2><<<blk, 256>>>(vq, vsh);

    cudaError_t e = cudaFuncSetAttribute(fused_attn,
        cudaFuncAttributeMaxDynamicSharedMemorySize, SMEM_TOTAL);
    if (e != cudaSuccess)
        fprintf(stderr, "[kl] attr: %s\n", cudaGetErrorString(e));

    dim3 grid(TD / QTILE, BHN);     // 32 x 32
    fused_attn<<<grid, THREADS, SMEM_TOTAL>>>((float*)d_out);
    diag_sync("fused_attn");
}

// round 13
// speedup vs baseline: 2.6363x; 1.0894x over previous
#include <cuda_runtime.h>
#include <cuda_bf16.h>
#include <math.h>
#include <stdio.h>
#include <stdint.h>

// Dims
#define BHN 32
#define TD 1024
#define SD 1024
#define HCD 128
#define QTILE 32           // q rows per CTA (K1)
#define NCH 8              // S chunks of 128 (K1)
#define THREADS 512        // K1 threads
#define N_ELEM (BHN * TD * HCD)

// K1 smem strides (elements)
#define QS 136             // q tile row stride, bf16
#define KS 136             // k tile row stride, bf16
#define PS 1036            // score row stride, f32
#define SMEM_P_BYTES  (QTILE * PS * 4)            // 132,608
#define SMEM_Q_BYTES  (QTILE * QS * 2)            //   8,704
#define SMEM_K_BYTES  (128 * KS * 2)              //  34,816 per buffer
#define SMEM_K1 (SMEM_P_BYTES + SMEM_Q_BYTES + 2 * SMEM_K_BYTES)   // 210,944

// K2 (RV GEMM) config
#define TS2 72             // 64-col tile row stride, bf16 (144B; %128=16 -> ldsm conflict-free)
#define SMEM_K2 (4 * 128 * TS2 * 2)               // A0,B0,A1,B1 = 73,728

// ------------- bf16 scratch (device globals) -------------------------------
__device__ __align__(128) __nv_bfloat16 g_qb[N_ELEM];    // [bh][t][c]
__device__ __align__(128) __nv_bfloat16 g_kb[N_ELEM];    // [bh][s][c]
__device__ __align__(128) __nv_bfloat16 g_vtb[N_ELEM];   // [bh][c][s]
__device__ __align__(128) __nv_bfloat16 g_r[(size_t)BHN * TD * SD];  // [bh][t][s] 64MB

// ---------------- pre-pass dequant: (q << s) exact in bf16 -----------------
template <int DST>
__global__ __launch_bounds__(256)
void dequant4(const int* __restrict__ q, const int* __restrict__ s)
{
    __nv_bfloat16* out = (DST == 0) ? g_qb : (DST == 1) ? g_kb : g_vtb;
    int i = blockIdx.x * 256 + threadIdx.x;            // int4 index (exact grid)
    int4 v = ((const int4*)q)[i];
    int m = 1 << (s[i >> 1] & 31);
    __nv_bfloat16 o[4];
    o[0] = __float2bfloat16_rn((float)(v.x * m));
    o[1] = __float2bfloat16_rn((float)(v.y * m));
    o[2] = __float2bfloat16_rn((float)(v.z * m));
    o[3] = __float2bfloat16_rn((float)(v.w * m));
    ((uint2*)out)[i] = *(const uint2*)o;
}

__device__ __forceinline__ void mma16816(float c[4], const uint32_t a[4], const uint32_t b[2])
{
    asm volatile(
        "mma.sync.aligned.m16n8k16.row.col.f32.bf16.bf16.f32 "
        "{%0,%1,%2,%3}, {%4,%5,%6,%7}, {%8,%9}, {%0,%1,%2,%3};\n"
        : "+f"(c[0]), "+f"(c[1]), "+f"(c[2]), "+f"(c[3])
        : "r"(a[0]), "r"(a[1]), "r"(a[2]), "r"(a[3]), "r"(b[0]), "r"(b[1]));
}

__device__ __forceinline__ void ldsm_x4(uint32_t r[4], uint32_t addr)
{
    asm volatile("ldmatrix.sync.aligned.m8n8.x4.shared.b16 {%0,%1,%2,%3}, [%4];"
                 : "=r"(r[0]), "=r"(r[1]), "=r"(r[2]), "=r"(r[3]) : "r"(addr));
}

__device__ __forceinline__ uint32_t smem_u32(const void* p)
{
    return (uint32_t)__cvta_generic_to_shared(p);
}

__device__ __forceinline__ uint32_t f2bf2(float lo, float hi)
{
    __nv_bfloat162 h = __floats2bfloat162_rn(lo, hi);
    return *(uint32_t*)&h;
}

// ============================ K1: QK + softmax + requant ====================
__global__ __launch_bounds__(THREADS)
void qk_softmax()
{
    extern __shared__ char sm[];
    float*         Ps  = (float*)sm;                                   // 32 x PS f32
    __nv_bfloat16* Qs  = (__nv_bfloat16*)(sm + SMEM_P_BYTES);          // 32 x QS
    __nv_bfloat16* Kv0 = (__nv_bfloat16*)(sm + SMEM_P_BYTES + SMEM_Q_BYTES);
    __nv_bfloat16* Kv1 = Kv0 + 128 * KS;

    const int bh   = blockIdx.y;
    const int t0   = blockIdx.x * QTILE;
    const int tid  = threadIdx.x;
    const int lane = tid & 31;
    const int wid  = tid >> 5;
    const int wm   = wid & 1;           // m-half (16 rows)
    const int wn   = wid >> 1;          // 0..7 (16-col slice)
    const int fr   = lane >> 2;
    const int fc   = (lane & 3) << 1;

    const uint32_t aQ = smem_u32(&Qs[(wm * 16 + (lane & 15)) * QS + ((lane >> 4) << 3)]);
    const uint32_t bKV0 = smem_u32(&Kv0[(wn * 16 + (lane & 7) + ((lane >> 4) << 3)) * KS
                                        + (((lane >> 3) & 1) << 3)]);
    const uint32_t bKV1 = bKV0 + SMEM_K_BYTES;

    const int crow = tid >> 4;          // 0..31
    const int cseg = tid & 15;          // 0..15

    // Q tile copy (32 x 128 bf16 = 512 uint4)
    {
        const uint4* src = (const uint4*)(g_qb + ((size_t)bh * TD + t0) * HCD);
        *(uint4*)&Qs[crow * QS + cseg * 8] = src[crow * 16 + cseg];
    }

    uint4 pre4[4];

#define LOAD_K(CH)                                                         \
    {                                                                      \
        const uint4* src = (const uint4*)(g_kb + ((size_t)bh * SD + (CH) * 128) * HCD); \
        _Pragma("unroll")                                                  \
        for (int i = 0; i < 4; i++) pre4[i] = src[tid + i * THREADS];      \
    }

#define STS_KV(BUF)                                                        \
    {                                                                      \
        _Pragma("unroll")                                                  \
        for (int i = 0; i < 4; i++) {                                      \
            int u = tid + i * THREADS;                                     \
            *(uint4*)&(BUF)[(u >> 4) * KS + (u & 15) * 8] = pre4[i];       \
        }                                                                  \
    }

    LOAD_K(0);
    STS_KV(Kv0);
    __syncthreads();

    uint32_t afq[8][4];
#pragma unroll
    for (int ks = 0; ks < 8; ks++) ldsm_x4(afq[ks], aQ + ks * 32);

    for (int ch = 0; ch < NCH; ch++) {
        if (ch + 1 < NCH) LOAD_K(ch + 1);
        const uint32_t bB = (ch & 1) ? bKV1 : bKV0;

        float acc[2][4];
#pragma unroll
        for (int nt = 0; nt < 2; nt++)
#pragma unroll
            for (int i = 0; i < 4; i++) acc[nt][i] = 0.f;

#pragma unroll
        for (int ks = 0; ks < 8; ks++) {
            uint32_t b[4];
            ldsm_x4(b, bB + ks * 32);
            mma16816(acc[0], afq[ks], b);
            mma16816(acc[1], afq[ks], b + 2);
        }
#pragma unroll
        for (int nt = 0; nt < 2; nt++) {
            int col = ch * 128 + wn * 16 + nt * 8 + fc;
            int r0 = (wm * 16 + fr) * PS;
            *(float2*)&Ps[r0 + col]          = make_float2(acc[nt][0], acc[nt][1]);
            *(float2*)&Ps[r0 + 8 * PS + col] = make_float2(acc[nt][2], acc[nt][3]);
        }
        if (ch + 1 < NCH) STS_KV((ch & 1) ? Kv0 : Kv1);
        __syncthreads();
    }

    // -------- single-pass softmax + requant, scores kept in registers ------
    {
        const float SCALE = (float)(6.103515625e-05 / sqrt(128.0)); // f32(2^-14/sqrt(HC))
        const int srow = tid >> 4;      // 0..31
        const int tr   = tid & 15;
        float* P = Ps + srow * PS;

        float4 v[16];                   // 64 scores in regs (read Ps ONCE)
#pragma unroll
        for (int j = 0; j < 8; j++) {
            v[2 * j]     = *(const float4*)(P + (tr + 16 * j) * 8);
            v[2 * j + 1] = *(const float4*)(P + (tr + 16 * j) * 8 + 4);
        }

        float mx = -3.0e38f;
#pragma unroll
        for (int i = 0; i < 16; i++)
            mx = fmaxf(mx, fmaxf(fmaxf(v[i].x, v[i].y), fmaxf(v[i].z, v[i].w)));
        mx = fmaxf(mx, __shfl_xor_sync(0xffffffffu, mx, 1));
        mx = fmaxf(mx, __shfl_xor_sync(0xffffffffu, mx, 2));
        mx = fmaxf(mx, __shfl_xor_sync(0xffffffffu, mx, 4));
        mx = fmaxf(mx, __shfl_xor_sync(0xffffffffu, mx, 8));
        const float lm = mx * SCALE;

        float sum = 0.f;
#pragma unroll
        for (int i = 0; i < 16; i++) {
            v[i].x = expf(v[i].x * SCALE - lm);
            v[i].y = expf(v[i].y * SCALE - lm);
            v[i].z = expf(v[i].z * SCALE - lm);
            v[i].w = expf(v[i].w * SCALE - lm);
            sum += (v[i].x + v[i].y) + (v[i].z + v[i].w);
        }
        sum += __shfl_xor_sync(0xffffffffu, sum, 1);
        sum += __shfl_xor_sync(0xffffffffu, sum, 2);
        sum += __shfl_xor_sync(0xffffffffu, sum, 4);
        sum += __shfl_xor_sync(0xffffffffu, sum, 8);

        __nv_bfloat16* rout = g_r + ((size_t)bh * TD + t0 + srow) * SD;
#pragma unroll
        for (int j = 0; j < 8; j++) {
            float4 x0 = v[2 * j], x1 = v[2 * j + 1];
            float val[8];
            val[0] = rintf(__fdiv_rn(x0.x, sum) * 16384.0f);   // half-even == jnp.round
            val[1] = rintf(__fdiv_rn(x0.y, sum) * 16384.0f);
            val[2] = rintf(__fdiv_rn(x0.z, sum) * 16384.0f);
            val[3] = rintf(__fdiv_rn(x0.w, sum) * 16384.0f);
            val[4] = rintf(__fdiv_rn(x1.x, sum) * 16384.0f);
            val[5] = rintf(__fdiv_rn(x1.y, sum) * 16384.0f);
            val[6] = rintf(__fdiv_rn(x1.z, sum) * 16384.0f);
            val[7] = rintf(__fdiv_rn(x1.w, sum) * 16384.0f);
            float g = fmaxf(fmaxf(fmaxf(val[0], val[1]), fmaxf(val[2], val[3])),
                            fmaxf(fmaxf(val[4], val[5]), fmaxf(val[6], val[7])));
            int gi = (int)g;                        // <= 16384
            int vv = (gi + 254) / 255;              // ceil(gi/255)
            int k  = (vv > 1) ? (32 - __clz(vv - 1)) : 0;    // clip(ceil(log2(g/255)),0)
            float dn = __int_as_float((127 - k) << 23);      // exact 2^-k
            float up = __int_as_float((127 + k) << 23);      // exact 2^k
            float r0 = fminf(rintf(val[0] * dn), 255.0f) * up;
            float r1 = fminf(rintf(val[1] * dn), 255.0f) * up;
            float r2 = fminf(rintf(val[2] * dn), 255.0f) * up;
            float r3 = fminf(rintf(val[3] * dn), 255.0f) * up;
            float r4 = fminf(rintf(val[4] * dn), 255.0f) * up;
            float r5 = fminf(rintf(val[5] * dn), 255.0f) * up;
            float r6 = fminf(rintf(val[6] * dn), 255.0f) * up;
            float r7 = fminf(rintf(val[7] * dn), 255.0f) * up;
            uint4 o;
            o.x = f2bf2(r0, r1);                    // exact: <=8-bit mantissa * po2
            o.y = f2bf2(r2, r3);
            o.z = f2bf2(r4, r5);
            o.w = f2bf2(r6, r7);
            *(uint4*)&rout[(tr + 16 * j) * 8] = o;  // coalesced 16B stores
        }
    }
}

// ============================ K2: RV GEMM ==================================
// out[bh][t][c] = r[bh][t][s] @ vt[bh][c][s]^T ; 128x128 tile, K=1024, cp.async
#define CPA16(dst, srcp) \
    asm volatile("cp.async.cg.shared.global [%0], [%1], 16;\n" :: "r"(dst), "l"(srcp))

template <int N>
__device__ __forceinline__ void cp_wait()
{
    asm volatile("cp.async.wait_group %0;\n" :: "n"(N));
}

__global__ __launch_bounds__(256, 2)
void rv_gemm(float* __restrict__ out)
{
    extern __shared__ char sm[];
    __nv_bfloat16* A0 = (__nv_bfloat16*)sm;         // 128 x TS2
    __nv_bfloat16* B0 = A0 + 128 * TS2;
    // buffer 1 offset = 2*128*TS2 elements = 36,864 bytes

    const int bh  = blockIdx.y;
    const int m0  = blockIdx.x * 128;
    const int tid = threadIdx.x;
    const int lane = tid & 31;
    const int warp = tid >> 5;
    const int wm   = warp & 1;          // 64-row half
    const int wn   = warp >> 1;         // 0..3, 32-col slice
    const int fr   = lane >> 2;
    const int fc   = (lane & 3) << 1;

    const __nv_bfloat16* Ag = g_r  + (size_t)bh * TD * SD + (size_t)m0 * SD;
    const __nv_bfloat16* Bg = g_vtb + (size_t)bh * HCD * SD;

    const int lrow = tid >> 3;          // 0..31 (x4 iters -> 128 rows)
    const int lseg = tid & 7;           // 0..7

#define LOADCH(KC, AOFF)                                                      \
    {                                                                         \
        uint32_t abase = smem_u32(A0) + (AOFF);                               \
        uint32_t bbase = smem_u32(B0) + (AOFF);                               \
        _Pragma("unroll")                                                     \
        for (int i = 0; i < 4; i++) {                                         \
            int row = lrow + i * 32;                                          \
            CPA16(abase + (row * TS2 + lseg * 8) * 2,                         \
                  Ag + (size_t)row * SD + (KC) * 64 + lseg * 8);              \
            CPA16(bbase + (row * TS2 + lseg * 8) * 2,                         \
                  Bg + (size_t)row * SD + (KC) * 64 + lseg * 8);              \
        }                                                                     \
        asm volatile("cp.async.commit_group;\n" ::: "memory");                \
    }

    const uint32_t aA = smem_u32(A0)
        + ((wm * 64 + (lane & 15)) * TS2 + ((lane >> 4) << 3)) * 2;
    const uint32_t bB = smem_u32(B0)
        + ((wn * 32 + (lane & 7) + ((lane >> 4) << 3)) * TS2 + (((lane >> 3) & 1) << 3)) * 2;

    float acc[4][4][4];
#pragma unroll
    for (int mf = 0; mf < 4; mf++)
#pragma unroll
        for (int nt = 0; nt < 4; nt++)
#pragma unroll
            for (int i = 0; i < 4; i++) acc[mf][nt][i] = 0.f;

    LOADCH(0, 0);

    for (int kc = 0; kc < 16; kc++) {
        const uint32_t boff = (kc & 1) ? 36864u : 0u;
        if (kc + 1 < 16) {
            LOADCH(kc + 1, (kc & 1) ? 0u : 36864u);
            cp_wait<1>();
        } else {
            cp_wait<0>();
        }
        __syncthreads();

#pragma unroll
        for (int ks = 0; ks < 4; ks++) {
            uint32_t a[4][4], b[2][4];
#pragma unroll
            for (int mf = 0; mf < 4; mf++)
                ldsm_x4(a[mf], aA + boff + mf * (16 * TS2 * 2) + ks * 32);
#pragma unroll
            for (int p = 0; p < 2; p++)
                ldsm_x4(b[p], bB + boff + p * (16 * TS2 * 2) + ks * 32);
#pragma unroll
            for (int mf = 0; mf < 4; mf++)
#pragma unroll
                for (int p = 0; p < 2; p++) {
                    mma16816(acc[mf][2 * p],     a[mf], b[p]);
                    mma16816(acc[mf][2 * p + 1], a[mf], b[p] + 2);
                }
        }
        __syncthreads();
    }

    // epilogue
    float* C = out + (size_t)bh * TD * HCD;
#pragma unroll
    for (int mf = 0; mf < 4; mf++) {
#pragma unroll
        for (int nt = 0; nt < 4; nt++) {
            int row = m0 + wm * 64 + mf * 16 + fr;
            int col = wn * 32 + (nt >> 1) * 16 + (nt & 1) * 8 + fc;
            *(float2*)&C[(size_t)row * HCD + col] =
                make_float2(rintf(acc[mf][nt][0]), rintf(acc[mf][nt][1]));
            *(float2*)&C[(size_t)(row + 8) * HCD + col] =
                make_float2(rintf(acc[mf][nt][2]), rintf(acc[mf][nt][3]));
        }
    }
}

// ---------------------------------------------------------------------------
static void diag_sync(const char* stage)
{
    cudaStreamCaptureStatus st = cudaStreamCaptureStatusNone;
    cudaStreamIsCapturing(0, &st);
    if (st == cudaStreamCaptureStatusNone) {
        cudaError_t e = cudaStreamSynchronize(0);
        if (e != cudaSuccess)
            fprintf(stderr, "[kl] stage %s: %s\n", stage, cudaGetErrorString(e));
    }
}

extern "C" void kernel_launch(void* const* d_in, const int* in_sizes, int n_in,
                              void* d_out, int out_size)
{
    if (n_in < 6) { fprintf(stderr, "[kl] bad n_in=%d\n", n_in); return; }

    const int* qq  = (const int*)d_in[0];
    const int* qsh = (const int*)d_in[1];
    const int* kq  = (const int*)d_in[2];
    const int* ksh = (const int*)d_in[3];
    const int* vq  = (const int*)d_in[4];
    const int* vsh = (const int*)d_in[5];

    const int blk = N_ELEM / 4 / 256;               // 4096, exact
    dequant4<0><<<blk, 256>>>(qq, qsh);
    dequant4<1><<<blk, 256>>>(kq, ksh);
    dequant4<2><<<blk, 256>>>(vq, vsh);

    static int attr_done = 0;
    if (!attr_done) {
        cudaFuncSetAttribute(qk_softmax,
            cudaFuncAttributeMaxDynamicSharedMemorySize, SMEM_K1);
        cudaFuncSetAttribute(rv_gemm,
            cudaFuncAttributeMaxDynamicSharedMemorySize, SMEM_K2);
        attr_done = 1;
    }

    dim3 g1(TD / QTILE, BHN);     // 32 x 32
    qk_softmax<<<g1, THREADS, SMEM_K1>>>();

    dim3 g2(TD / 128, BHN);       // 8 x 32 = 256 CTAs (single wave at 2/SM)
    rv_gemm<<<g2, 256, SMEM_K2>>>((float*)d_out);
    diag_sync("split");
}

// round 14
// speedup vs baseline: 2.9660x; 1.1251x over previous
#include <cuda_runtime.h>
#include <cuda_bf16.h>
#include <math.h>
#include <stdio.h>
#include <stdint.h>

// Dims
#define BHN 32
#define TD 1024
#define SD 1024
#define HCD 128
#define QTILE 32           // q rows per CTA (K1)
#define NCH 8              // S chunks of 128 (K1)
#define THREADS 512        // K1 threads
#define N_ELEM (BHN * TD * HCD)

// K1 smem layout
#define QS 136             // q tile row stride, bf16
#define KS 136             // k tile row stride, bf16
#define KVBUF (128 * KS * 2)                      // 34,816 per buffer
#define SMEM_QS 8704                              // 32*136*2
#define SMEM_KV_OFF SMEM_QS
#define SMEM_RED_OFF (SMEM_QS + 4 * KVBUF)        // 147,968
#define SMEM_K1 (SMEM_RED_OFF + 2048)             // 150,016

// K2 (RV GEMM) config
#define TS2 72             // 64-col tile row stride, bf16
#define SMEM_K2 (4 * 128 * TS2 * 2)               // 73,728

// ------------- bf16 scratch (device globals) -------------------------------
__device__ __align__(128) __nv_bfloat16 g_kb[N_ELEM];    // [bh][s][c]
__device__ __align__(128) __nv_bfloat16 g_vtb[N_ELEM];   // [bh][c][s]
__device__ __align__(128) __nv_bfloat16 g_r[(size_t)BHN * TD * SD];  // [bh][t][s]

// ---------------- pre-pass dequant (K, VT only): exact in bf16 -------------
template <int DST>
__global__ __launch_bounds__(256)
void dequant4(const int* __restrict__ q, const int* __restrict__ s)
{
    __nv_bfloat16* out = (DST == 0) ? g_kb : g_vtb;
    int i = blockIdx.x * 256 + threadIdx.x;            // int4 index (exact grid)
    int4 v = ((const int4*)q)[i];
    int m = 1 << (s[i >> 1] & 31);
    __nv_bfloat16 o[4];
    o[0] = __float2bfloat16_rn((float)(v.x * m));
    o[1] = __float2bfloat16_rn((float)(v.y * m));
    o[2] = __float2bfloat16_rn((float)(v.z * m));
    o[3] = __float2bfloat16_rn((float)(v.w * m));
    ((uint2*)out)[i] = *(const uint2*)o;
}

__device__ __forceinline__ void mma16816(float c[4], const uint32_t a[4], const uint32_t b[2])
{
    asm volatile(
        "mma.sync.aligned.m16n8k16.row.col.f32.bf16.bf16.f32 "
        "{%0,%1,%2,%3}, {%4,%5,%6,%7}, {%8,%9}, {%0,%1,%2,%3};\n"
        : "+f"(c[0]), "+f"(c[1]), "+f"(c[2]), "+f"(c[3])
        : "r"(a[0]), "r"(a[1]), "r"(a[2]), "r"(a[3]), "r"(b[0]), "r"(b[1]));
}

__device__ __forceinline__ void ldsm_x4(uint32_t r[4], uint32_t addr)
{
    asm volatile("ldmatrix.sync.aligned.m8n8.x4.shared.b16 {%0,%1,%2,%3}, [%4];"
                 : "=r"(r[0]), "=r"(r[1]), "=r"(r[2]), "=r"(r[3]) : "r"(addr));
}

__device__ __forceinline__ uint32_t smem_u32(const void* p)
{
    return (uint32_t)__cvta_generic_to_shared(p);
}

__device__ __forceinline__ uint32_t f2bf2(float lo, float hi)
{
    __nv_bfloat162 h = __floats2bfloat162_rn(lo, hi);
    return *(uint32_t*)&h;
}

#define CPA16(dst, srcp) \
    asm volatile("cp.async.cg.shared.global [%0], [%1], 16;\n" :: "r"(dst), "l"(srcp))
#define CPA_COMMIT() asm volatile("cp.async.commit_group;\n" ::: "memory")
template <int N>
__device__ __forceinline__ void cp_wait()
{
    asm volatile("cp.async.wait_group %0;\n" :: "n"(N));
}

// ============================ K1: QK + softmax + requant ====================
// Scores live entirely in registers (acc[8][2][4] = 64 f32/thread).
__global__ __launch_bounds__(THREADS)
void qk_softmax(const int* __restrict__ qq, const int* __restrict__ qsh)
{
    extern __shared__ char sm[];
    __nv_bfloat16* Qs   = (__nv_bfloat16*)sm;               // 32 x QS
    char*          Kv   = sm + SMEM_KV_OFF;                  // 4 x (128 x KS)
    float*         redM = (float*)(sm + SMEM_RED_OFF);       // [32][8]
    float*         redS = redM + 256;                        // [32][8]

    const int bh   = blockIdx.y;
    const int t0   = blockIdx.x * QTILE;
    const int tid  = threadIdx.x;
    const int lane = tid & 31;
    const int wid  = tid >> 5;
    const int wm   = wid & 1;           // m-half (16 rows)
    const int wn   = wid >> 1;          // 0..7 (16-col slice per chunk)
    const int fr   = lane >> 2;         // fragment row 0..7
    const int fc   = (lane & 3) << 1;   // fragment col {0,2,4,6}

    const uint32_t aQ  = smem_u32(&Qs[(wm * 16 + (lane & 15)) * QS + ((lane >> 4) << 3)]);
    const uint32_t bKV = smem_u32(Kv)
        + ((wn * 16 + (lane & 7) + ((lane >> 4) << 3)) * KS + (((lane >> 3) & 1) << 3)) * 2;

    const __nv_bfloat16* Kg = g_kb + (size_t)bh * SD * HCD;

#define LOADK(CH, BUF)                                                        \
    {                                                                         \
        const __nv_bfloat16* src = Kg + (size_t)(CH) * 128 * HCD;             \
        uint32_t base = smem_u32(Kv) + (BUF) * KVBUF;                         \
        _Pragma("unroll")                                                     \
        for (int i = 0; i < 4; i++) {                                         \
            int u = tid + i * THREADS;                                        \
            int row = u >> 4, seg = u & 15;                                   \
            CPA16(base + (row * KS + seg * 8) * 2,                            \
                  src + (size_t)row * HCD + seg * 8);                         \
        }                                                                     \
        CPA_COMMIT();                                                         \
    }

    // prologue: start K pipeline, then inline-dequant q tile
    LOADK(0, 0);
    LOADK(1, 1);
    {
        const int* qb = qq  + ((size_t)bh * TD + t0) * HCD;
        const int* sb = qsh + ((size_t)bh * TD + t0) * 16;
#pragma unroll
        for (int i = 0; i < 2; i++) {                      // 1024 int4 / 512 thr
            int u = tid + i * THREADS;
            int row = u >> 5, c4 = u & 31;
            int4 v = *(const int4*)(qb + (size_t)row * HCD + c4 * 4);
            int m = 1 << (sb[row * 16 + (c4 >> 1)] & 31);
            __nv_bfloat16 o[4];
            o[0] = __float2bfloat16_rn((float)(v.x * m));
            o[1] = __float2bfloat16_rn((float)(v.y * m));
            o[2] = __float2bfloat16_rn((float)(v.z * m));
            o[3] = __float2bfloat16_rn((float)(v.w * m));
            *(uint2*)&Qs[row * QS + c4 * 4] = *(const uint2*)o;
        }
    }
    LOADK(2, 2);
    cp_wait<2>();                      // group 0 complete
    __syncthreads();                   // Qs + Kv buf0 visible

    uint32_t afq[8][4];
#pragma unroll
    for (int ks = 0; ks < 8; ks++) ldsm_x4(afq[ks], aQ + ks * 32);

    float acc[8][2][4];
#pragma unroll
    for (int ch = 0; ch < 8; ch++)
#pragma unroll
        for (int nt = 0; nt < 2; nt++)
#pragma unroll
            for (int i = 0; i < 4; i++) acc[ch][nt][i] = 0.f;

#pragma unroll
    for (int ch = 0; ch < NCH; ch++) {
        if (ch > 0) {
            if (ch <= 5)      cp_wait<2>();
            else if (ch == 6) cp_wait<1>();
            else              cp_wait<0>();
            __syncthreads();
        }
        const uint32_t bB = bKV + (ch & 3) * KVBUF;
#pragma unroll
        for (int ks = 0; ks < 8; ks++) {
            uint32_t b[4];
            ldsm_x4(b, bB + ks * 32);
            mma16816(acc[ch][0], afq[ks], b);
            mma16816(acc[ch][1], afq[ks], b + 2);
        }
        if (ch + 3 < NCH) LOADK(ch + 3, (ch + 3) & 3);
    }

    // -------- softmax + requant, fully register-resident --------------
    const float SCALE = (float)(6.103515625e-05 / sqrt(128.0)); // f32(2^-14/sqrt(HC))
    const int row0 = wm * 16 + fr;
    const int row1 = row0 + 8;

    // row maxima
    float m0 = -3.0e38f, m1 = -3.0e38f;
#pragma unroll
    for (int ch = 0; ch < 8; ch++)
#pragma unroll
        for (int nt = 0; nt < 2; nt++) {
            m0 = fmaxf(m0, fmaxf(acc[ch][nt][0], acc[ch][nt][1]));
            m1 = fmaxf(m1, fmaxf(acc[ch][nt][2], acc[ch][nt][3]));
        }
    m0 = fmaxf(m0, __shfl_xor_sync(0xffffffffu, m0, 1));
    m0 = fmaxf(m0, __shfl_xor_sync(0xffffffffu, m0, 2));
    m1 = fmaxf(m1, __shfl_xor_sync(0xffffffffu, m1, 1));
    m1 = fmaxf(m1, __shfl_xor_sync(0xffffffffu, m1, 2));
    if ((lane & 3) == 0) {
        redM[row0 * 8 + wn] = m0;
        redM[row1 * 8 + wn] = m1;
    }
    __syncthreads();
    float mx0 = -3.0e38f, mx1 = -3.0e38f;
#pragma unroll
    for (int j = 0; j < 8; j++) {
        mx0 = fmaxf(mx0, redM[row0 * 8 + j]);
        mx1 = fmaxf(mx1, redM[row1 * 8 + j]);
    }
    const float lm0 = mx0 * SCALE;
    const float lm1 = mx1 * SCALE;

    // exp + row sums (e overwrites acc)
    float s0 = 0.f, s1 = 0.f;
#pragma unroll
    for (int ch = 0; ch < 8; ch++)
#pragma unroll
        for (int nt = 0; nt < 2; nt++) {
            acc[ch][nt][0] = expf(acc[ch][nt][0] * SCALE - lm0);
            acc[ch][nt][1] = expf(acc[ch][nt][1] * SCALE - lm0);
            acc[ch][nt][2] = expf(acc[ch][nt][2] * SCALE - lm1);
            acc[ch][nt][3] = expf(acc[ch][nt][3] * SCALE - lm1);
            s0 += acc[ch][nt][0] + acc[ch][nt][1];
            s1 += acc[ch][nt][2] + acc[ch][nt][3];
        }
    s0 += __shfl_xor_sync(0xffffffffu, s0, 1);
    s0 += __shfl_xor_sync(0xffffffffu, s0, 2);
    s1 += __shfl_xor_sync(0xffffffffu, s1, 1);
    s1 += __shfl_xor_sync(0xffffffffu, s1, 2);
    if ((lane & 3) == 0) {
        redS[row0 * 8 + wn] = s0;
        redS[row1 * 8 + wn] = s1;
    }
    __syncthreads();
    float sum0 = 0.f, sum1 = 0.f;
#pragma unroll
    for (int j = 0; j < 8; j++) {
        sum0 += redS[row0 * 8 + j];
        sum1 += redS[row1 * 8 + j];
    }

    // requant: group of 8 cols = 4 lanes x 2 vals (same fr quadrant)
    __nv_bfloat16* rout = g_r + ((size_t)bh * TD + t0) * SD;
#pragma unroll
    for (int ch = 0; ch < 8; ch++) {
#pragma unroll
        for (int nt = 0; nt < 2; nt++) {
            int col = ch * 128 + wn * 16 + nt * 8 + fc;
            // row0
            {
                float v0 = rintf(__fdiv_rn(acc[ch][nt][0], sum0) * 16384.0f);
                float v1 = rintf(__fdiv_rn(acc[ch][nt][1], sum0) * 16384.0f);
                float g = fmaxf(v0, v1);
                g = fmaxf(g, __shfl_xor_sync(0xffffffffu, g, 1));
                g = fmaxf(g, __shfl_xor_sync(0xffffffffu, g, 2));
                int gi = (int)g;                       // <= 16384
                int vv = (gi + 254) / 255;             // ceil(gi/255)
                int k  = (vv > 1) ? (32 - __clz(vv - 1)) : 0;
                float dn = __int_as_float((127 - k) << 23);   // exact 2^-k
                float up = __int_as_float((127 + k) << 23);   // exact 2^k
                float r0 = fminf(rintf(v0 * dn), 255.0f) * up;
                float r1 = fminf(rintf(v1 * dn), 255.0f) * up;
                *(uint32_t*)&rout[(size_t)row0 * SD + col] = f2bf2(r0, r1);
            }
            // row1
            {
                float v0 = rintf(__fdiv_rn(acc[ch][nt][2], sum1) * 16384.0f);
                float v1 = rintf(__fdiv_rn(acc[ch][nt][3], sum1) * 16384.0f);
                float g = fmaxf(v0, v1);
                g = fmaxf(g, __shfl_xor_sync(0xffffffffu, g, 1));
                g = fmaxf(g, __shfl_xor_sync(0xffffffffu, g, 2));
                int gi = (int)g;
                int vv = (gi + 254) / 255;
                int k  = (vv > 1) ? (32 - __clz(vv - 1)) : 0;
                float dn = __int_as_float((127 - k) << 23);
                float up = __int_as_float((127 + k) << 23);
                float r0 = fminf(rintf(v0 * dn), 255.0f) * up;
                float r1 = fminf(rintf(v1 * dn), 255.0f) * up;
                *(uint32_t*)&rout[(size_t)row1 * SD + col] = f2bf2(r0, r1);
            }
        }
    }
}

// ============================ K2: RV GEMM ==================================
// out[bh][t][c] = r[bh][t][s] @ vt[bh][c][s]^T ; 128x128 tile, K=1024, cp.async
__global__ __launch_bounds__(256, 2)
void rv_gemm(float* __restrict__ out)
{
    extern __shared__ char sm[];
    __nv_bfloat16* A0 = (__nv_bfloat16*)sm;         // 128 x TS2
    __nv_bfloat16* B0 = A0 + 128 * TS2;

    const int bh  = blockIdx.y;
    const int m0  = blockIdx.x * 128;
    const int tid = threadIdx.x;
    const int lane = tid & 31;
    const int warp = tid >> 5;
    const int wm   = warp & 1;          // 64-row half
    const int wn   = warp >> 1;         // 0..3, 32-col slice
    const int fr   = lane >> 2;
    const int fc   = (lane & 3) << 1;

    const __nv_bfloat16* Ag = g_r   + (size_t)bh * TD * SD + (size_t)m0 * SD;
    const __nv_bfloat16* Bg = g_vtb + (size_t)bh * HCD * SD;

    const int lrow = tid >> 3;          // 0..31 (x4 iters -> 128 rows)
    const int lseg = tid & 7;           // 0..7

#define LOADCH(KC, AOFF)                                                      \
    {                                                                         \
        uint32_t abase = smem_u32(A0) + (AOFF);                               \
        uint32_t bbase = smem_u32(B0) + (AOFF);                               \
        _Pragma("unroll")                                                     \
        for (int i = 0; i < 4; i++) {                                         \
            int row = lrow + i * 32;                                          \
            CPA16(abase + (row * TS2 + lseg * 8) * 2,                         \
                  Ag + (size_t)row * SD + (KC) * 64 + lseg * 8);              \
            CPA16(bbase + (row * TS2 + lseg * 8) * 2,                         \
                  Bg + (size_t)row * SD + (KC) * 64 + lseg * 8);              \
        }                                                                     \
        CPA_COMMIT();                                                         \
    }

    const uint32_t aA = smem_u32(A0)
        + ((wm * 64 + (lane & 15)) * TS2 + ((lane >> 4) << 3)) * 2;
    const uint32_t bB = smem_u32(B0)
        + ((wn * 32 + (lane & 7) + ((lane >> 4) << 3)) * TS2 + (((lane >> 3) & 1) << 3)) * 2;

    float acc[4][4][4];
#pragma unroll
    for (int mf = 0; mf < 4; mf++)
#pragma unroll
        for (int nt = 0; nt < 4; nt++)
#pragma unroll
            for (int i = 0; i < 4; i++) acc[mf][nt][i] = 0.f;

    LOADCH(0, 0);

    for (int kc = 0; kc < 16; kc++) {
        const uint32_t boff = (kc & 1) ? 36864u : 0u;
        if (kc + 1 < 16) {
            LOADCH(kc + 1, (kc & 1) ? 0u : 36864u);
            cp_wait<1>();
        } else {
            cp_wait<0>();
        }
        __syncthreads();

#pragma unroll
        for (int ks = 0; ks < 4; ks++) {
            uint32_t a[4][4], b[2][4];
#pragma unroll
            for (int mf = 0; mf < 4; mf++)
                ldsm_x4(a[mf], aA + boff + mf * (16 * TS2 * 2) + ks * 32);
#pragma unroll
            for (int p = 0; p < 2; p++)
                ldsm_x4(b[p], bB + boff + p * (16 * TS2 * 2) + ks * 32);
#pragma unroll
            for (int mf = 0; mf < 4; mf++)
#pragma unroll
                for (int p = 0; p < 2; p++) {
                    mma16816(acc[mf][2 * p],     a[mf], b[p]);
                    mma16816(acc[mf][2 * p + 1], a[mf], b[p] + 2);
                }
        }
        __syncthreads();
    }

    float* C = out + (size_t)bh * TD * HCD;
#pragma unroll
    for (int mf = 0; mf < 4; mf++) {
#pragma unroll
        for (int nt = 0; nt < 4; nt++) {
            int row = m0 + wm * 64 + mf * 16 + fr;
            int col = wn * 32 + (nt >> 1) * 16 + (nt & 1) * 8 + fc;
            *(float2*)&C[(size_t)row * HCD + col] =
                make_float2(rintf(acc[mf][nt][0]), rintf(acc[mf][nt][1]));
            *(float2*)&C[(size_t)(row + 8) * HCD + col] =
                make_float2(rintf(acc[mf][nt][2]), rintf(acc[mf][nt][3]));
        }
    }
}

// ---------------------------------------------------------------------------
static void diag_sync(const char* stage)
{
    cudaStreamCaptureStatus st = cudaStreamCaptureStatusNone;
    cudaStreamIsCapturing(0, &st);
    if (st == cudaStreamCaptureStatusNone) {
        cudaError_t e = cudaStreamSynchronize(0);
        if (e != cudaSuccess)
            fprintf(stderr, "[kl] stage %s: %s\n", stage, cudaGetErrorString(e));
    }
}

extern "C" void kernel_launch(void* const* d_in, const int* in_sizes, int n_in,
                              void* d_out, int out_size)
{
    if (n_in < 6) { fprintf(stderr, "[kl] bad n_in=%d\n", n_in); return; }

    const int* qq  = (const int*)d_in[0];
    const int* qsh = (const int*)d_in[1];
    const int* kq  = (const int*)d_in[2];
    const int* ksh = (const int*)d_in[3];
    const int* vq  = (const int*)d_in[4];
    const int* vsh = (const int*)d_in[5];

    const int blk = N_ELEM / 4 / 256;               // 4096, exact
    dequant4<0><<<blk, 256>>>(kq, ksh);
    dequant4<1><<<blk, 256>>>(vq, vsh);

    static int attr_done = 0;
    if (!attr_done) {
        cudaFuncSetAttribute(qk_softmax,
            cudaFuncAttributeMaxDynamicSharedMemorySize, SMEM_K1);
        cudaFuncSetAttribute(rv_gemm,
            cudaFuncAttributeMaxDynamicSharedMemorySize, SMEM_K2);
        attr_done = 1;
    }

    dim3 g1(TD / QTILE, BHN);     // 32 x 32
    qk_softmax<<<g1, THREADS, SMEM_K1>>>(qq, qsh);

    dim3 g2(TD / 128, BHN);       // 8 x 32 = 256 CTAs
    rv_gemm<<<g2, 256, SMEM_K2>>>((float*)d_out);
    diag_sync("split");
}

// round 15
// speedup vs baseline: 3.1956x; 1.0774x over previous
#include <cuda_runtime.h>
#include <cuda_bf16.h>
#include <math.h>
#include <stdio.h>
#include <stdint.h>

// Dims
#define BHN 32
#define TD 1024
#define SD 1024
#define HCD 128
#define QTILE 32           // q rows per CTA (K1)
#define NCH 8              // S chunks of 128 (K1)
#define THREADS 512        // K1 threads
#define N_ELEM (BHN * TD * HCD)

// K1 smem layout
#define QS 136             // q tile row stride, bf16
#define KS 136             // k tile row stride, bf16
#define KVBUF (128 * KS * 2)                      // 34,816 per buffer
#define SMEM_QS 8704                              // 32*136*2
#define SMEM_KV_OFF SMEM_QS
#define SMEM_RED_OFF (SMEM_QS + 4 * KVBUF)        // 147,968
#define SMEM_K1 (SMEM_RED_OFF + 2048)             // 150,016

// K2 (RV GEMM) config: 3-stage cp.async
#define TS2 72             // 64-col tile row stride, bf16
#define K2STAGE (2 * 128 * TS2 * 2)               // A+B per stage = 36,864
#define SMEM_K2 (3 * K2STAGE)                     // 110,592

// ------------- bf16 scratch (device globals) -------------------------------
__device__ __align__(128) __nv_bfloat16 g_kb[N_ELEM];    // [bh][s][c]
__device__ __align__(128) __nv_bfloat16 g_vtb[N_ELEM];   // [bh][c][s]
__device__ __align__(128) __nv_bfloat16 g_r[(size_t)BHN * TD * SD];  // [bh][t][s]

// ---------------- pre-pass dequant (K + VT in one launch) ------------------
__global__ __launch_bounds__(256)
void dequant2(const int* __restrict__ kq, const int* __restrict__ ksh,
              const int* __restrict__ vq, const int* __restrict__ vsh)
{
    const int* q = blockIdx.y ? vq : kq;
    const int* s = blockIdx.y ? vsh : ksh;
    __nv_bfloat16* out = blockIdx.y ? g_vtb : g_kb;
    int i = blockIdx.x * 256 + threadIdx.x;            // int4 index (exact grid)
    int4 v = ((const int4*)q)[i];
    int m = 1 << (s[i >> 1] & 31);
    __nv_bfloat16 o[4];
    o[0] = __float2bfloat16_rn((float)(v.x * m));
    o[1] = __float2bfloat16_rn((float)(v.y * m));
    o[2] = __float2bfloat16_rn((float)(v.z * m));
    o[3] = __float2bfloat16_rn((float)(v.w * m));
    ((uint2*)out)[i] = *(const uint2*)o;
}

__device__ __forceinline__ void mma16816(float c[4], const uint32_t a[4], const uint32_t b[2])
{
    asm volatile(
        "mma.sync.aligned.m16n8k16.row.col.f32.bf16.bf16.f32 "
        "{%0,%1,%2,%3}, {%4,%5,%6,%7}, {%8,%9}, {%0,%1,%2,%3};\n"
        : "+f"(c[0]), "+f"(c[1]), "+f"(c[2]), "+f"(c[3])
        : "r"(a[0]), "r"(a[1]), "r"(a[2]), "r"(a[3]), "r"(b[0]), "r"(b[1]));
}

__device__ __forceinline__ void ldsm_x4(uint32_t r[4], uint32_t addr)
{
    asm volatile("ldmatrix.sync.aligned.m8n8.x4.shared.b16 {%0,%1,%2,%3}, [%4];"
                 : "=r"(r[0]), "=r"(r[1]), "=r"(r[2]), "=r"(r[3]) : "r"(addr));
}

__device__ __forceinline__ uint32_t smem_u32(const void* p)
{
    return (uint32_t)__cvta_generic_to_shared(p);
}

__device__ __forceinline__ uint32_t f2bf2(float lo, float hi)
{
    __nv_bfloat162 h = __floats2bfloat162_rn(lo, hi);
    return *(uint32_t*)&h;
}

#define CPA16(dst, srcp) \
    asm volatile("cp.async.cg.shared.global [%0], [%1], 16;\n" :: "r"(dst), "l"(srcp))
#define CPA_COMMIT() asm volatile("cp.async.commit_group;\n" ::: "memory")
template <int N>
__device__ __forceinline__ void cp_wait()
{
    asm volatile("cp.async.wait_group %0;\n" :: "n"(N));
}

// ============================ K1: QK + softmax + requant ====================
// Scores live entirely in registers (acc[8][2][4] = 64 f32/thread).
__global__ __launch_bounds__(THREADS)
void qk_softmax(const int* __restrict__ qq, const int* __restrict__ qsh)
{
    extern __shared__ char sm[];
    __nv_bfloat16* Qs   = (__nv_bfloat16*)sm;               // 32 x QS
    char*          Kv   = sm + SMEM_KV_OFF;                  // 4 x (128 x KS)
    float*         redM = (float*)(sm + SMEM_RED_OFF);       // [32][8]
    float*         redS = redM + 256;                        // [32][8]

    const int bh   = blockIdx.y;
    const int t0   = blockIdx.x * QTILE;
    const int tid  = threadIdx.x;
    const int lane = tid & 31;
    const int wid  = tid >> 5;
    const int wm   = wid & 1;           // m-half (16 rows)
    const int wn   = wid >> 1;          // 0..7 (16-col slice per chunk)
    const int fr   = lane >> 2;         // fragment row 0..7
    const int fc   = (lane & 3) << 1;   // fragment col {0,2,4,6}

    const uint32_t aQ  = smem_u32(&Qs[(wm * 16 + (lane & 15)) * QS + ((lane >> 4) << 3)]);
    const uint32_t bKV = smem_u32(Kv)
        + ((wn * 16 + (lane & 7) + ((lane >> 4) << 3)) * KS + (((lane >> 3) & 1) << 3)) * 2;

    const __nv_bfloat16* Kg = g_kb + (size_t)bh * SD * HCD;

#define LOADK(CH, BUF)                                                        \
    {                                                                         \
        const __nv_bfloat16* src = Kg + (size_t)(CH) * 128 * HCD;             \
        uint32_t base = smem_u32(Kv) + (BUF) * KVBUF;                         \
        _Pragma("unroll")                                                     \
        for (int i = 0; i < 4; i++) {                                         \
            int u = tid + i * THREADS;                                        \
            int row = u >> 4, seg = u & 15;                                   \
            CPA16(base + (row * KS + seg * 8) * 2,                            \
                  src + (size_t)row * HCD + seg * 8);                         \
        }                                                                     \
        CPA_COMMIT();                                                         \
    }

    // prologue: start K pipeline, then inline-dequant q tile
    LOADK(0, 0);
    LOADK(1, 1);
    {
        const int* qb = qq  + ((size_t)bh * TD + t0) * HCD;
        const int* sb = qsh + ((size_t)bh * TD + t0) * 16;
#pragma unroll
        for (int i = 0; i < 2; i++) {                      // 1024 int4 / 512 thr
            int u = tid + i * THREADS;
            int row = u >> 5, c4 = u & 31;
            int4 v = *(const int4*)(qb + (size_t)row * HCD + c4 * 4);
            int m = 1 << (sb[row * 16 + (c4 >> 1)] & 31);
            __nv_bfloat16 o[4];
            o[0] = __float2bfloat16_rn((float)(v.x * m));
            o[1] = __float2bfloat16_rn((float)(v.y * m));
            o[2] = __float2bfloat16_rn((float)(v.z * m));
            o[3] = __float2bfloat16_rn((float)(v.w * m));
            *(uint2*)&Qs[row * QS + c4 * 4] = *(const uint2*)o;
        }
    }
    LOADK(2, 2);
    cp_wait<2>();                      // group 0 complete
    __syncthreads();                   // Qs + Kv buf0 visible

    uint32_t afq[8][4];
#pragma unroll
    for (int ks = 0; ks < 8; ks++) ldsm_x4(afq[ks], aQ + ks * 32);

    float acc[8][2][4];
#pragma unroll
    for (int ch = 0; ch < 8; ch++)
#pragma unroll
        for (int nt = 0; nt < 2; nt++)
#pragma unroll
            for (int i = 0; i < 4; i++) acc[ch][nt][i] = 0.f;

#pragma unroll
    for (int ch = 0; ch < NCH; ch++) {
        if (ch > 0) {
            if (ch <= 5)      cp_wait<2>();
            else if (ch == 6) cp_wait<1>();
            else              cp_wait<0>();
            __syncthreads();
        }
        const uint32_t bB = bKV + (ch & 3) * KVBUF;
#pragma unroll
        for (int ks = 0; ks < 8; ks++) {
            uint32_t b[4];
            ldsm_x4(b, bB + ks * 32);
            mma16816(acc[ch][0], afq[ks], b);
            mma16816(acc[ch][1], afq[ks], b + 2);
        }
        if (ch + 3 < NCH) LOADK(ch + 3, (ch + 3) & 3);
    }

    // -------- softmax + requant, fully register-resident --------------
    const float SCALE = (float)(6.103515625e-05 / sqrt(128.0)); // f32(2^-14/sqrt(HC))
    const int row0 = wm * 16 + fr;
    const int row1 = row0 + 8;

    // row maxima
    float m0 = -3.0e38f, m1 = -3.0e38f;
#pragma unroll
    for (int ch = 0; ch < 8; ch++)
#pragma unroll
        for (int nt = 0; nt < 2; nt++) {
            m0 = fmaxf(m0, fmaxf(acc[ch][nt][0], acc[ch][nt][1]));
            m1 = fmaxf(m1, fmaxf(acc[ch][nt][2], acc[ch][nt][3]));
        }
    m0 = fmaxf(m0, __shfl_xor_sync(0xffffffffu, m0, 1));
    m0 = fmaxf(m0, __shfl_xor_sync(0xffffffffu, m0, 2));
    m1 = fmaxf(m1, __shfl_xor_sync(0xffffffffu, m1, 1));
    m1 = fmaxf(m1, __shfl_xor_sync(0xffffffffu, m1, 2));
    if ((lane & 3) == 0) {
        redM[row0 * 8 + wn] = m0;
        redM[row1 * 8 + wn] = m1;
    }
    __syncthreads();
    float mx0 = -3.0e38f, mx1 = -3.0e38f;
#pragma unroll
    for (int j = 0; j < 8; j++) {
        mx0 = fmaxf(mx0, redM[row0 * 8 + j]);
        mx1 = fmaxf(mx1, redM[row1 * 8 + j]);
    }
    const float lm0 = mx0 * SCALE;
    const float lm1 = mx1 * SCALE;

    // exp + row sums (e overwrites acc)
    float s0 = 0.f, s1 = 0.f;
#pragma unroll
    for (int ch = 0; ch < 8; ch++)
#pragma unroll
        for (int nt = 0; nt < 2; nt++) {
            acc[ch][nt][0] = expf(acc[ch][nt][0] * SCALE - lm0);
            acc[ch][nt][1] = expf(acc[ch][nt][1] * SCALE - lm0);
            acc[ch][nt][2] = expf(acc[ch][nt][2] * SCALE - lm1);
            acc[ch][nt][3] = expf(acc[ch][nt][3] * SCALE - lm1);
            s0 += acc[ch][nt][0] + acc[ch][nt][1];
            s1 += acc[ch][nt][2] + acc[ch][nt][3];
        }
    s0 += __shfl_xor_sync(0xffffffffu, s0, 1);
    s0 += __shfl_xor_sync(0xffffffffu, s0, 2);
    s1 += __shfl_xor_sync(0xffffffffu, s1, 1);
    s1 += __shfl_xor_sync(0xffffffffu, s1, 2);
    if ((lane & 3) == 0) {
        redS[row0 * 8 + wn] = s0;
        redS[row1 * 8 + wn] = s1;
    }
    __syncthreads();
    float sum0 = 0.f, sum1 = 0.f;
#pragma unroll
    for (int j = 0; j < 8; j++) {
        sum0 += redS[row0 * 8 + j];
        sum1 += redS[row1 * 8 + j];
    }
    // one exact division per row; per-element becomes a single multiply
    const float rs0 = __fdiv_rn(16384.0f, sum0);
    const float rs1 = __fdiv_rn(16384.0f, sum1);

    // requant: group of 8 cols = 4 lanes x 2 vals (same fr quadrant)
    __nv_bfloat16* rout = g_r + ((size_t)bh * TD + t0) * SD;
#pragma unroll
    for (int ch = 0; ch < 8; ch++) {
#pragma unroll
        for (int nt = 0; nt < 2; nt++) {
            int col = ch * 128 + wn * 16 + nt * 8 + fc;
            // row0
            {
                float v0 = rintf(acc[ch][nt][0] * rs0);
                float v1 = rintf(acc[ch][nt][1] * rs0);
                float g = fmaxf(v0, v1);
                g = fmaxf(g, __shfl_xor_sync(0xffffffffu, g, 1));
                g = fmaxf(g, __shfl_xor_sync(0xffffffffu, g, 2));
                int gi = (int)g;                       // <= 16384
                int vv = (gi + 254) / 255;             // ceil(gi/255)
                int k  = (vv > 1) ? (32 - __clz(vv - 1)) : 0;
                float dn = __int_as_float((127 - k) << 23);   // exact 2^-k
                float up = __int_as_float((127 + k) << 23);   // exact 2^k
                float r0 = fminf(rintf(v0 * dn), 255.0f) * up;
                float r1 = fminf(rintf(v1 * dn), 255.0f) * up;
                *(uint32_t*)&rout[(size_t)row0 * SD + col] = f2bf2(r0, r1);
            }
            // row1
            {
                float v0 = rintf(acc[ch][nt][2] * rs1);
                float v1 = rintf(acc[ch][nt][3] * rs1);
                float g = fmaxf(v0, v1);
                g = fmaxf(g, __shfl_xor_sync(0xffffffffu, g, 1));
                g = fmaxf(g, __shfl_xor_sync(0xffffffffu, g, 2));
                int gi = (int)g;
                int vv = (gi + 254) / 255;
                int k  = (vv > 1) ? (32 - __clz(vv - 1)) : 0;
                float dn = __int_as_float((127 - k) << 23);
                float up = __int_as_float((127 + k) << 23);
                float r0 = fminf(rintf(v0 * dn), 255.0f) * up;
                float r1 = fminf(rintf(v1 * dn), 255.0f) * up;
                *(uint32_t*)&rout[(size_t)row1 * SD + col] = f2bf2(r0, r1);
            }
        }
    }
}

// ============================ K2: RV GEMM (3-stage) =========================
// out[bh][t][c] = r[bh][t][s] @ vt[bh][c][s]^T ; 128x128 tile, K=1024
__global__ __launch_bounds__(256, 2)
void rv_gemm(float* __restrict__ out)
{
    extern __shared__ char sm[];
    __nv_bfloat16* A0 = (__nv_bfloat16*)sm;         // stage: A(128xTS2) + B(128xTS2)
    __nv_bfloat16* B0 = A0 + 128 * TS2;

    const int bh  = blockIdx.y;
    const int m0  = blockIdx.x * 128;
    const int tid = threadIdx.x;
    const int lane = tid & 31;
    const int warp = tid >> 5;
    const int wm   = warp & 1;          // 64-row half
    const int wn   = warp >> 1;         // 0..3, 32-col slice
    const int fr   = lane >> 2;
    const int fc   = (lane & 3) << 1;

    const __nv_bfloat16* Ag = g_r   + (size_t)bh * TD * SD + (size_t)m0 * SD;
    const __nv_bfloat16* Bg = g_vtb + (size_t)bh * HCD * SD;

    const int lrow = tid >> 3;          // 0..31 (x4 iters -> 128 rows)
    const int lseg = tid & 7;           // 0..7

#define LOADCH(KC)                                                            \
    {                                                                         \
        uint32_t off = ((KC) % 3) * (uint32_t)K2STAGE;                        \
        uint32_t abase = smem_u32(A0) + off;                                  \
        uint32_t bbase = smem_u32(B0) + off;                                  \
        _Pragma("unroll")                                                     \
        for (int i = 0; i < 4; i++) {                                         \
            int row = lrow + i * 32;                                          \
            CPA16(abase + (row * TS2 + lseg * 8) * 2,                         \
                  Ag + (size_t)row * SD + (KC) * 64 + lseg * 8);              \
            CPA16(bbase + (row * TS2 + lseg * 8) * 2,                         \
                  Bg + (size_t)row * SD + (KC) * 64 + lseg * 8);              \
        }                                                                     \
        CPA_COMMIT();                                                         \
    }

    const uint32_t aA = smem_u32(A0)
        + ((wm * 64 + (lane & 15)) * TS2 + ((lane >> 4) << 3)) * 2;
    const uint32_t bB = smem_u32(B0)
        + ((wn * 32 + (lane & 7) + ((lane >> 4) << 3)) * TS2 + (((lane >> 3) & 1) << 3)) * 2;

    float acc[4][4][4];
#pragma unroll
    for (int mf = 0; mf < 4; mf++)
#pragma unroll
        for (int nt = 0; nt < 4; nt++)
#pragma unroll
            for (int i = 0; i < 4; i++) acc[mf][nt][i] = 0.f;

    LOADCH(0);
    LOADCH(1);

    for (int kc = 0; kc < 16; kc++) {
        if (kc + 2 < 16) {
            LOADCH(kc + 2);
            cp_wait<2>();
        } else if (kc + 2 == 16) {
            cp_wait<1>();
        } else {
            cp_wait<0>();
        }
        __syncthreads();

        const uint32_t boff = (kc % 3) * (uint32_t)K2STAGE;
#pragma unroll
        for (int ks = 0; ks < 4; ks++) {
            uint32_t a[4][4], b[2][4];
#pragma unroll
            for (int mf = 0; mf < 4; mf++)
                ldsm_x4(a[mf], aA + boff + mf * (16 * TS2 * 2) + ks * 32);
#pragma unroll
            for (int p = 0; p < 2; p++)
                ldsm_x4(b[p], bB + boff + p * (16 * TS2 * 2) + ks * 32);
#pragma unroll
            for (int mf = 0; mf < 4; mf++)
#pragma unroll
                for (int p = 0; p < 2; p++) {
                    mma16816(acc[mf][2 * p],     a[mf], b[p]);
                    mma16816(acc[mf][2 * p + 1], a[mf], b[p] + 2);
                }
        }
        __syncthreads();
    }

    float* C = out + (size_t)bh * TD * HCD;
#pragma unroll
    for (int mf = 0; mf < 4; mf++) {
#pragma unroll
        for (int nt = 0; nt < 4; nt++) {
            int row = m0 + wm * 64 + mf * 16 + fr;
            int col = wn * 32 + (nt >> 1) * 16 + (nt & 1) * 8 + fc;
            *(float2*)&C[(size_t)row * HCD + col] =
                make_float2(rintf(acc[mf][nt][0]), rintf(acc[mf][nt][1]));
            *(float2*)&C[(size_t)(row + 8) * HCD + col] =
                make_float2(rintf(acc[mf][nt][2]), rintf(acc[mf][nt][3]));
        }
    }
}

// ---------------------------------------------------------------------------
static void diag_sync(const char* stage)
{
    cudaStreamCaptureStatus st = cudaStreamCaptureStatusNone;
    cudaStreamIsCapturing(0, &st);
    if (st == cudaStreamCaptureStatusNone) {
        cudaError_t e = cudaStreamSynchronize(0);
        if (e != cudaSuccess)
            fprintf(stderr, "[kl] stage %s: %s\n", stage, cudaGetErrorString(e));
    }
}

extern "C" void kernel_launch(void* const* d_in, const int* in_sizes, int n_in,
                              void* d_out, int out_size)
{
    if (n_in < 6) { fprintf(stderr, "[kl] bad n_in=%d\n", n_in); return; }

    const int* qq  = (const int*)d_in[0];
    const int* qsh = (const int*)d_in[1];
    const int* kq  = (const int*)d_in[2];
    const int* ksh = (const int*)d_in[3];
    const int* vq  = (const int*)d_in[4];
    const int* vsh = (const int*)d_in[5];

    dim3 gd(N_ELEM / 4 / 256, 2);                   // 4096 x 2
    dequant2<<<gd, 256>>>(kq, ksh, vq, vsh);

    static int attr_done = 0;
    if (!attr_done) {
        cudaFuncSetAttribute(qk_softmax,
            cudaFuncAttributeMaxDynamicSharedMemorySize, SMEM_K1);
        cudaFuncSetAttribute(rv_gemm,
            cudaFuncAttributeMaxDynamicSharedMemorySize, SMEM_K2);
        attr_done = 1;
    }

    dim3 g1(TD / QTILE, BHN);     // 32 x 32
    qk_softmax<<<g1, THREADS, SMEM_K1>>>(qq, qsh);

    dim3 g2(TD / 128, BHN);       // 8 x 32 = 256 CTAs
    rv_gemm<<<g2, 256, SMEM_K2>>>((float*)d_out);
    diag_sync("split");
}